// round 1
// baseline (speedup 1.0000x reference)
#include <cuda_runtime.h>
#include <cuda_bf16.h>

#define NN 40000
#define EE 400000
#define GGR 64
#define IN_DIM 128
#define DD 64
#define HH 4
#define CC 10
#define HD 256   // H*D

// ---------------- static device scratch (no allocation allowed) ----------------
__device__ float g_feat[NN * HD];   // projected features of current layer
__device__ float g_h1[NN * HD];     // layer outputs ping
__device__ float g_h2[NN * HD];     // layer outputs pong
__device__ float g_el[NN * HH];
__device__ float g_er[NN * HH];
__device__ float g_e[EE * HH];      // leaky_relu(el[src]+er[dst])
__device__ int   g_counts[NN];
__device__ int   g_rowptr[NN + 1];
__device__ int   g_cursor[NN];
__device__ int   g_eids[EE];
__device__ float g_hg[GGR * DD];
__device__ float g_cnt[GGR];

// ---------------- CSR build ----------------
__global__ void hist_kernel(const int* __restrict__ dst) {
    int t = blockIdx.x * blockDim.x + threadIdx.x;
    if (t < EE) atomicAdd(&g_counts[dst[t]], 1);
}

__global__ void scan_kernel() {
    __shared__ int sh[1024];
    __shared__ int carry;
    int t = threadIdx.x;
    if (t == 0) { carry = 0; g_rowptr[0] = 0; }
    __syncthreads();
    for (int base = 0; base < NN; base += 1024) {
        int v = (base + t < NN) ? g_counts[base + t] : 0;
        sh[t] = v;
        __syncthreads();
        for (int off = 1; off < 1024; off <<= 1) {
            int add = (t >= off) ? sh[t - off] : 0;
            __syncthreads();
            sh[t] += add;
            __syncthreads();
        }
        int inc = sh[t] + carry;
        if (base + t < NN) g_rowptr[base + t + 1] = inc;
        int total = sh[1023];
        __syncthreads();
        if (t == 0) carry += total;
        __syncthreads();
    }
}

__global__ void scatter_kernel(const int* __restrict__ dst) {
    int t = blockIdx.x * blockDim.x + threadIdx.x;
    if (t < EE) {
        int d = dst[t];
        int pos = g_rowptr[d] + atomicAdd(&g_cursor[d], 1);
        g_eids[pos] = t;
    }
}

// ---------------- GEMM: C[M,256] = A[M,K] * B[K,256], M=40000 ----------------
// 64x64 tile, BK=16, 256 threads, 4x4 microtile per thread.
__global__ void gemm_kernel(const float* __restrict__ A, const float* __restrict__ B,
                            float* __restrict__ C, int K) {
    __shared__ float As[16][64];
    __shared__ float Bs[16][64];
    const int bm = blockIdx.y * 64;
    const int bn = blockIdx.x * 64;
    const int tid = threadIdx.x;
    const int tx = tid & 15;
    const int ty = tid >> 4;
    const int ar = tid >> 2, ac4 = tid & 3;   // A-load: row, float4-col
    const int br = tid >> 4, bc4 = tid & 15;  // B-load: row, float4-col

    float acc[4][4] = {};
    for (int k0 = 0; k0 < K; k0 += 16) {
        float4 a = *(const float4*)&A[(size_t)(bm + ar) * K + k0 + ac4 * 4];
        float4 b = *(const float4*)&B[(size_t)(k0 + br) * HD + bn + bc4 * 4];
        As[ac4 * 4 + 0][ar] = a.x;
        As[ac4 * 4 + 1][ar] = a.y;
        As[ac4 * 4 + 2][ar] = a.z;
        As[ac4 * 4 + 3][ar] = a.w;
        *(float4*)&Bs[br][bc4 * 4] = b;
        __syncthreads();
#pragma unroll
        for (int k = 0; k < 16; k++) {
            float4 av = *(const float4*)&As[k][ty * 4];
            float4 bv = *(const float4*)&Bs[k][tx * 4];
            float avv[4] = {av.x, av.y, av.z, av.w};
            float bvv[4] = {bv.x, bv.y, bv.z, bv.w};
#pragma unroll
            for (int i = 0; i < 4; i++)
#pragma unroll
                for (int j = 0; j < 4; j++)
                    acc[i][j] += avv[i] * bvv[j];
        }
        __syncthreads();
    }
#pragma unroll
    for (int i = 0; i < 4; i++) {
        float4 r = make_float4(acc[i][0], acc[i][1], acc[i][2], acc[i][3]);
        *(float4*)&C[(size_t)(bm + ty * 4 + i) * HD + bn + tx * 4] = r;
    }
}

// ---------------- el/er: per (node, head) warp dot products ----------------
__global__ void elr_kernel(const float* __restrict__ al, const float* __restrict__ ar) {
    // 256 threads = 8 warps = 2 nodes x 4 heads
    int warp = threadIdx.x >> 5;
    int lane = threadIdx.x & 31;
    int n = blockIdx.x * 2 + (warp >> 2);
    int h = warp & 3;
    const float* f = &g_feat[(size_t)n * HD + h * DD];
    float f0 = f[lane], f1 = f[lane + 32];
    float pl = f0 * al[h * DD + lane] + f1 * al[h * DD + lane + 32];
    float pr = f0 * ar[h * DD + lane] + f1 * ar[h * DD + lane + 32];
#pragma unroll
    for (int off = 16; off; off >>= 1) {
        pl += __shfl_xor_sync(0xffffffffu, pl, off);
        pr += __shfl_xor_sync(0xffffffffu, pr, off);
    }
    if (lane == 0) {
        g_el[n * HH + h] = pl;
        g_er[n * HH + h] = pr;
    }
}

// ---------------- per-edge attention logits ----------------
__global__ void edge_kernel(const int* __restrict__ src, const int* __restrict__ dst) {
    int t = blockIdx.x * blockDim.x + threadIdx.x;
    if (t >= EE) return;
    int s = src[t], d = dst[t];
#pragma unroll
    for (int h = 0; h < HH; h++) {
        float e = g_el[s * HH + h] + g_er[d * HH + h];
        g_e[t * HH + h] = e > 0.f ? e : 0.2f * e;
    }
}

// ---------------- per-node softmax + aggregation ----------------
// one block per node, 4 warps = 4 heads
__global__ void agg_kernel(const int* __restrict__ src, const float* __restrict__ hin,
                           float* __restrict__ hout, int residual, int activate) {
    int n = blockIdx.x;
    int h = threadIdx.x >> 5;
    int lane = threadIdx.x & 31;
    int s0 = g_rowptr[n];
    int deg = g_rowptr[n + 1] - s0;

    float o0 = 0.f, o1 = 0.f;
    if (deg > 0) {
        // pass 1: max over in-edges
        float m = -1e30f;
        for (int i = lane; i < deg; i += 32) {
            int eid = g_eids[s0 + i];
            m = fmaxf(m, g_e[eid * HH + h]);
        }
#pragma unroll
        for (int off = 16; off; off >>= 1)
            m = fmaxf(m, __shfl_xor_sync(0xffffffffu, m, off));
        // pass 2: exp-weighted accumulate (all lanes walk edges together)
        float a0 = 0.f, a1 = 0.f, sw = 0.f;
        for (int i = 0; i < deg; i++) {
            int eid = g_eids[s0 + i];
            float w = __expf(g_e[eid * HH + h] - m);
            int sn = src[eid];
            const float* f = &g_feat[(size_t)sn * HD + h * DD];
            a0 += w * f[lane];
            a1 += w * f[lane + 32];
            sw += w;
        }
        float inv = 1.f / fmaxf(sw, 1e-9f);
        o0 = a0 * inv;
        o1 = a1 * inv;
    }
    if (residual) {
        o0 += hin[(size_t)n * HD + h * DD + lane];
        o1 += hin[(size_t)n * HD + h * DD + lane + 32];
    }
    if (activate) {
        o0 = o0 > 0.f ? o0 : (__expf(o0) - 1.f);
        o1 = o1 > 0.f ? o1 : (__expf(o1) - 1.f);
    }
    hout[(size_t)n * HD + h * DD + lane] = o0;
    hout[(size_t)n * HD + h * DD + lane + 32] = o1;
}

// ---------------- readout: mean over heads, segment-sum over graphs ----------------
__global__ void readout_kernel(const float* __restrict__ hfin, const int* __restrict__ gid) {
    // 256 threads = 8 warps, one node per warp
    int warp = threadIdx.x >> 5;
    int lane = threadIdx.x & 31;
    int n = blockIdx.x * 8 + warp;
    if (n >= NN) return;
    int g = gid[n];
    const float* f = &hfin[(size_t)n * HD];
    float v0 = 0.25f * (f[lane] + f[DD + lane] + f[2 * DD + lane] + f[3 * DD + lane]);
    float v1 = 0.25f * (f[lane + 32] + f[DD + lane + 32] + f[2 * DD + lane + 32] + f[3 * DD + lane + 32]);
    atomicAdd(&g_hg[g * DD + lane], v0);
    atomicAdd(&g_hg[g * DD + lane + 32], v1);
    if (lane == 0) atomicAdd(&g_cnt[g], 1.0f);
}

__global__ void classifier_kernel(const float* __restrict__ Wc, const float* __restrict__ bc,
                                  float* __restrict__ out) {
    int t = threadIdx.x;
    if (t >= GGR * CC) return;
    int g = t / CC, c = t % CC;
    float s = 0.f;
#pragma unroll
    for (int d = 0; d < DD; d++) s += g_hg[g * DD + d] * Wc[d * CC + c];
    out[t] = s / fmaxf(g_cnt[g], 1.0f) + bc[c];
}

// ---------------- host ----------------
extern "C" void kernel_launch(void* const* d_in, const int* in_sizes, int n_in,
                              void* d_out, int out_size) {
    const float* x   = (const float*)d_in[0];
    const int*   src = (const int*)d_in[1];
    const int*   dst = (const int*)d_in[2];
    const int*   gid = (const int*)d_in[3];
    const float* W0  = (const float*)d_in[4];
    const float* al0 = (const float*)d_in[5];
    const float* ar0 = (const float*)d_in[6];
    const float* W1  = (const float*)d_in[7];
    const float* al1 = (const float*)d_in[8];
    const float* ar1 = (const float*)d_in[9];
    const float* W2  = (const float*)d_in[10];
    const float* al2 = (const float*)d_in[11];
    const float* ar2 = (const float*)d_in[12];
    const float* Wc  = (const float*)d_in[13];
    const float* bc  = (const float*)d_in[14];
    float* out = (float*)d_out;

    void *p_counts, *p_cursor, *p_hg, *p_cnt, *p_feat, *p_h1, *p_h2;
    cudaGetSymbolAddress(&p_counts, g_counts);
    cudaGetSymbolAddress(&p_cursor, g_cursor);
    cudaGetSymbolAddress(&p_hg, g_hg);
    cudaGetSymbolAddress(&p_cnt, g_cnt);
    cudaGetSymbolAddress(&p_feat, g_feat);
    cudaGetSymbolAddress(&p_h1, g_h1);
    cudaGetSymbolAddress(&p_h2, g_h2);
    float* f_feat = (float*)p_feat;
    float* f_h1 = (float*)p_h1;
    float* f_h2 = (float*)p_h2;

    // CSR build (once; same graph for all 3 layers)
    cudaMemsetAsync(p_counts, 0, NN * sizeof(int));
    cudaMemsetAsync(p_cursor, 0, NN * sizeof(int));
    cudaMemsetAsync(p_hg, 0, GGR * DD * sizeof(float));
    cudaMemsetAsync(p_cnt, 0, GGR * sizeof(float));
    hist_kernel<<<(EE + 255) / 256, 256>>>(dst);
    scan_kernel<<<1, 1024>>>();
    scatter_kernel<<<(EE + 255) / 256, 256>>>(dst);

    dim3 ggrid(HD / 64, NN / 64);

    // ---- layer 0: x[N,128] -> h1 ----
    gemm_kernel<<<ggrid, 256>>>(x, W0, f_feat, IN_DIM);
    elr_kernel<<<NN / 2, 256>>>(al0, ar0);
    edge_kernel<<<(EE + 255) / 256, 256>>>(src, dst);
    agg_kernel<<<NN, 128>>>(src, nullptr, f_h1, 0, 1);

    // ---- layer 1: h1 -> h2 (residual) ----
    gemm_kernel<<<ggrid, 256>>>(f_h1, W1, f_feat, HD);
    elr_kernel<<<NN / 2, 256>>>(al1, ar1);
    edge_kernel<<<(EE + 255) / 256, 256>>>(src, dst);
    agg_kernel<<<NN, 128>>>(src, f_h1, f_h2, 1, 1);

    // ---- layer 2: h2 -> h1 (residual, no activation) ----
    gemm_kernel<<<ggrid, 256>>>(f_h2, W2, f_feat, HD);
    elr_kernel<<<NN / 2, 256>>>(al2, ar2);
    edge_kernel<<<(EE + 255) / 256, 256>>>(src, dst);
    agg_kernel<<<NN, 128>>>(src, f_h2, f_h1, 1, 0);

    // ---- readout + classifier ----
    readout_kernel<<<NN / 8, 256>>>(f_h1, gid);
    classifier_kernel<<<1, GGR * CC>>>(Wc, bc, out);
}

// round 2
// speedup vs baseline: 1.3842x; 1.3842x over previous
#include <cuda_runtime.h>
#include <cuda_bf16.h>

#define NN 40000
#define EE 400000
#define GGR 64
#define IN_DIM 128
#define DD 64
#define HH 4
#define CC 10
#define HD 256   // H*D

// ---------------- static device scratch ----------------
__device__ float g_feat[NN * HD];
__device__ float g_h1[NN * HD];
__device__ float g_h2[NN * HD];
__device__ float g_el[NN * HH];
__device__ float g_er[NN * HH];
__device__ float g_lmax[8];        // [0..3]=el max per head, [4..7]=er max per head
__device__ int   g_counts[NN];
__device__ int   g_rowptr[NN + 1];
__device__ int   g_cursor[NN];
__device__ int   g_esrc[EE];       // src node id per CSR slot (dst-grouped)
__device__ float g_hg[GGR * DD];
__device__ float g_cnt[GGR];

__device__ __forceinline__ void atomicMaxFloat(float* addr, float value) {
    if (value >= 0.f)
        atomicMax((int*)addr, __float_as_int(value));
    else
        atomicMin((unsigned int*)addr, __float_as_uint(value));
}

// ---------------- CSR build ----------------
__global__ void hist_kernel(const int* __restrict__ dst) {
    int t = blockIdx.x * blockDim.x + threadIdx.x;
    if (t < EE) atomicAdd(&g_counts[dst[t]], 1);
}

__global__ void scan_kernel() {
    __shared__ int sh[1024];
    const int PER = 40;  // 1024*40 >= NN
    int t = threadIdx.x;
    int base = t * PER;
    int s = 0;
    for (int k = 0; k < PER; k++) {
        int idx = base + k;
        if (idx < NN) s += g_counts[idx];
    }
    sh[t] = s;
    __syncthreads();
    for (int off = 1; off < 1024; off <<= 1) {
        int v = (t >= off) ? sh[t - off] : 0;
        __syncthreads();
        sh[t] += v;
        __syncthreads();
    }
    int run = (t > 0) ? sh[t - 1] : 0;
    if (t == 0) g_rowptr[0] = 0;
    for (int k = 0; k < PER; k++) {
        int idx = base + k;
        if (idx < NN) {
            run += g_counts[idx];
            g_rowptr[idx + 1] = run;
        }
    }
}

__global__ void scatter_kernel(const int* __restrict__ dst, const int* __restrict__ src) {
    int t = blockIdx.x * blockDim.x + threadIdx.x;
    if (t < EE) {
        int d = dst[t];
        int pos = g_rowptr[d] + atomicAdd(&g_cursor[d], 1);
        g_esrc[pos] = src[t];
    }
}

// ---------------- GEMM + fused el/er epilogue ----------------
// C[M,256] = A[M,K]*B[K,256]; tile 64x64, BK=16, 128 threads, 8x4 microtile.
// blockIdx.x = head (N-tile == one head's D=64 slice).
__global__ void gemm_fused_kernel(const float* __restrict__ A, const float* __restrict__ B,
                                  float* __restrict__ C, int K,
                                  const float* __restrict__ al, const float* __restrict__ arv) {
    __shared__ float As[16][68];
    __shared__ float Bs[16][68];
    __shared__ float redl[16], redr[16];
    const int bm = blockIdx.y * 64;
    const int h  = blockIdx.x;
    const int bn = h * 64;
    const int tid = threadIdx.x;
    const int tx = tid & 15;
    const int ty = tid >> 4;
    const int a_row = tid >> 2;   // 0..31 (+u*32)
    const int a_c   = tid & 3;    // 16B chunk
    const int b_row = tid >> 3;   // 0..15
    const int b_c   = tid & 7;    // chunk (+u*8)

    float acc[8][4] = {};

    for (int k0 = 0; k0 < K; k0 += 16) {
#pragma unroll
        for (int u = 0; u < 2; u++) {
            int row = a_row + u * 32;
            float4 a = *(const float4*)&A[(size_t)(bm + row) * K + k0 + a_c * 4];
            As[a_c * 4 + 0][row] = a.x;
            As[a_c * 4 + 1][row] = a.y;
            As[a_c * 4 + 2][row] = a.z;
            As[a_c * 4 + 3][row] = a.w;
        }
#pragma unroll
        for (int u = 0; u < 2; u++) {
            int c = b_c + u * 8;
            float4 b = *(const float4*)&B[(size_t)(k0 + b_row) * HD + bn + c * 4];
            *(float4*)&Bs[b_row][c * 4] = b;
        }
        __syncthreads();
#pragma unroll
        for (int k = 0; k < 16; k++) {
            float4 av0 = *(const float4*)&As[k][ty * 8];
            float4 av1 = *(const float4*)&As[k][ty * 8 + 4];
            float4 bv  = *(const float4*)&Bs[k][tx * 4];
            float am[8] = {av0.x, av0.y, av0.z, av0.w, av1.x, av1.y, av1.z, av1.w};
            float bb[4] = {bv.x, bv.y, bv.z, bv.w};
#pragma unroll
            for (int i = 0; i < 8; i++)
#pragma unroll
                for (int j = 0; j < 4; j++)
                    acc[i][j] = fmaf(am[i], bb[j], acc[i][j]);
        }
        __syncthreads();
    }

#pragma unroll
    for (int i = 0; i < 8; i++) {
        float4 r = make_float4(acc[i][0], acc[i][1], acc[i][2], acc[i][3]);
        *(float4*)&C[(size_t)(bm + ty * 8 + i) * HD + bn + tx * 4] = r;
    }

    // fused el/er: dot over this head's 64 cols, reduce across the 16-lane half-warp
    float4 alv = *(const float4*)&al[h * DD + tx * 4];
    float4 arw = *(const float4*)&arv[h * DD + tx * 4];
    float pls[8], prs[8];
#pragma unroll
    for (int i = 0; i < 8; i++) {
        float pl = acc[i][0] * alv.x + acc[i][1] * alv.y + acc[i][2] * alv.z + acc[i][3] * alv.w;
        float pr = acc[i][0] * arw.x + acc[i][1] * arw.y + acc[i][2] * arw.z + acc[i][3] * arw.w;
#pragma unroll
        for (int off = 8; off; off >>= 1) {
            pl += __shfl_xor_sync(0xffffffffu, pl, off);
            pr += __shfl_xor_sync(0xffffffffu, pr, off);
        }
        pls[i] = pl;
        prs[i] = pr;
    }
    if (tx == 0) {
        float mxl = -1e30f, mxr = -1e30f;
#pragma unroll
        for (int i = 0; i < 8; i++) {
            int n = bm + ty * 8 + i;
            g_el[n * HH + h] = pls[i];
            g_er[n * HH + h] = prs[i];
            mxl = fmaxf(mxl, pls[i]);
            mxr = fmaxf(mxr, prs[i]);
        }
        redl[ty] = mxl;
        redr[ty] = mxr;
    }
    __syncthreads();
    if (tid == 0) {
        float ml = -1e30f, mr = -1e30f;
#pragma unroll
        for (int i = 0; i < 16; i++) {
            ml = fmaxf(ml, redl[i]);
            mr = fmaxf(mr, redr[i]);
        }
        atomicMaxFloat(&g_lmax[h], ml);
        atomicMaxFloat(&g_lmax[4 + h], mr);
    }
}

// ---------------- single-pass softmax + aggregation ----------------
// one block per node, 4 warps = 4 heads; global-bound shift (exact softmax invariance)
__global__ void agg_kernel(const float* __restrict__ hin, float* __restrict__ hout,
                           int residual, int activate) {
    int n = blockIdx.x;
    int h = threadIdx.x >> 5;
    int lane = threadIdx.x & 31;
    int s0 = g_rowptr[n], s1 = g_rowptr[n + 1];
    float er_n = g_er[n * HH + h];
    float M = fmaxf(g_lmax[h] + g_lmax[4 + h], 0.f);
    float a0 = 0.f, a1 = 0.f, sw = 0.f;

    int i = s0;
    for (; i + 4 <= s1; i += 4) {
        int sA = g_esrc[i], sB = g_esrc[i + 1], sC = g_esrc[i + 2], sD = g_esrc[i + 3];
        float eA = g_el[sA * HH + h] + er_n;
        float eB = g_el[sB * HH + h] + er_n;
        float eC = g_el[sC * HH + h] + er_n;
        float eD = g_el[sD * HH + h] + er_n;
        eA = eA > 0.f ? eA : 0.2f * eA;
        eB = eB > 0.f ? eB : 0.2f * eB;
        eC = eC > 0.f ? eC : 0.2f * eC;
        eD = eD > 0.f ? eD : 0.2f * eD;
        float wA = __expf(eA - M), wB = __expf(eB - M);
        float wC = __expf(eC - M), wD = __expf(eD - M);
        const float* fA = &g_feat[(size_t)sA * HD + h * DD];
        const float* fB = &g_feat[(size_t)sB * HD + h * DD];
        const float* fC = &g_feat[(size_t)sC * HD + h * DD];
        const float* fD = &g_feat[(size_t)sD * HD + h * DD];
        float xA0 = fA[lane], xA1 = fA[lane + 32];
        float xB0 = fB[lane], xB1 = fB[lane + 32];
        float xC0 = fC[lane], xC1 = fC[lane + 32];
        float xD0 = fD[lane], xD1 = fD[lane + 32];
        a0 = fmaf(wA, xA0, fmaf(wB, xB0, fmaf(wC, xC0, fmaf(wD, xD0, a0))));
        a1 = fmaf(wA, xA1, fmaf(wB, xB1, fmaf(wC, xC1, fmaf(wD, xD1, a1))));
        sw += (wA + wB) + (wC + wD);
    }
    for (; i < s1; i++) {
        int s = g_esrc[i];
        float e = g_el[s * HH + h] + er_n;
        e = e > 0.f ? e : 0.2f * e;
        float w = __expf(e - M);
        const float* f = &g_feat[(size_t)s * HD + h * DD];
        a0 = fmaf(w, f[lane], a0);
        a1 = fmaf(w, f[lane + 32], a1);
        sw += w;
    }
    float inv = 1.f / fmaxf(sw, 1e-9f);
    float o0 = a0 * inv, o1 = a1 * inv;
    size_t base = (size_t)n * HD + h * DD;
    if (residual) {
        o0 += hin[base + lane];
        o1 += hin[base + lane + 32];
    }
    if (activate) {
        o0 = o0 > 0.f ? o0 : (__expf(o0) - 1.f);
        o1 = o1 > 0.f ? o1 : (__expf(o1) - 1.f);
    }
    hout[base + lane] = o0;
    hout[base + lane + 32] = o1;
}

// ---------------- readout + classifier ----------------
__global__ void readout_kernel(const float* __restrict__ hfin, const int* __restrict__ gid) {
    int warp = threadIdx.x >> 5;
    int lane = threadIdx.x & 31;
    int n = blockIdx.x * 8 + warp;
    if (n >= NN) return;
    int g = gid[n];
    const float* f = &hfin[(size_t)n * HD];
    float v0 = 0.25f * (f[lane] + f[DD + lane] + f[2 * DD + lane] + f[3 * DD + lane]);
    float v1 = 0.25f * (f[lane + 32] + f[DD + lane + 32] + f[2 * DD + lane + 32] + f[3 * DD + lane + 32]);
    atomicAdd(&g_hg[g * DD + lane], v0);
    atomicAdd(&g_hg[g * DD + lane + 32], v1);
    if (lane == 0) atomicAdd(&g_cnt[g], 1.0f);
}

__global__ void classifier_kernel(const float* __restrict__ Wc, const float* __restrict__ bc,
                                  float* __restrict__ out) {
    int t = threadIdx.x;
    if (t >= GGR * CC) return;
    int g = t / CC, c = t % CC;
    float s = 0.f;
#pragma unroll
    for (int d = 0; d < DD; d++) s += g_hg[g * DD + d] * Wc[d * CC + c];
    out[t] = s / fmaxf(g_cnt[g], 1.0f) + bc[c];
}

// ---------------- host ----------------
extern "C" void kernel_launch(void* const* d_in, const int* in_sizes, int n_in,
                              void* d_out, int out_size) {
    const float* x   = (const float*)d_in[0];
    const int*   src = (const int*)d_in[1];
    const int*   dst = (const int*)d_in[2];
    const int*   gid = (const int*)d_in[3];
    const float* W0  = (const float*)d_in[4];
    const float* al0 = (const float*)d_in[5];
    const float* ar0 = (const float*)d_in[6];
    const float* W1  = (const float*)d_in[7];
    const float* al1 = (const float*)d_in[8];
    const float* ar1 = (const float*)d_in[9];
    const float* W2  = (const float*)d_in[10];
    const float* al2 = (const float*)d_in[11];
    const float* ar2 = (const float*)d_in[12];
    const float* Wc  = (const float*)d_in[13];
    const float* bc  = (const float*)d_in[14];
    float* out = (float*)d_out;

    void *p_counts, *p_cursor, *p_hg, *p_cnt, *p_feat, *p_h1, *p_h2, *p_lmax;
    cudaGetSymbolAddress(&p_counts, g_counts);
    cudaGetSymbolAddress(&p_cursor, g_cursor);
    cudaGetSymbolAddress(&p_hg, g_hg);
    cudaGetSymbolAddress(&p_cnt, g_cnt);
    cudaGetSymbolAddress(&p_feat, g_feat);
    cudaGetSymbolAddress(&p_h1, g_h1);
    cudaGetSymbolAddress(&p_h2, g_h2);
    cudaGetSymbolAddress(&p_lmax, g_lmax);
    float* f_feat = (float*)p_feat;
    float* f_h1 = (float*)p_h1;
    float* f_h2 = (float*)p_h2;

    // CSR build (once; same graph for all 3 layers)
    cudaMemsetAsync(p_counts, 0, NN * sizeof(int));
    cudaMemsetAsync(p_cursor, 0, NN * sizeof(int));
    cudaMemsetAsync(p_hg, 0, GGR * DD * sizeof(float));
    cudaMemsetAsync(p_cnt, 0, GGR * sizeof(float));
    hist_kernel<<<(EE + 255) / 256, 256>>>(dst);
    scan_kernel<<<1, 1024>>>();
    scatter_kernel<<<(EE + 255) / 256, 256>>>(dst, src);

    dim3 ggrid(HH, NN / 64);

    // ---- layer 0 ----
    cudaMemsetAsync(p_lmax, 0xFF, 8 * sizeof(float));
    gemm_fused_kernel<<<ggrid, 128>>>(x, W0, f_feat, IN_DIM, al0, ar0);
    agg_kernel<<<NN, 128>>>(nullptr, f_h1, 0, 1);

    // ---- layer 1 (residual) ----
    cudaMemsetAsync(p_lmax, 0xFF, 8 * sizeof(float));
    gemm_fused_kernel<<<ggrid, 128>>>(f_h1, W1, f_feat, HD, al1, ar1);
    agg_kernel<<<NN, 128>>>(f_h1, f_h2, 1, 1);

    // ---- layer 2 (residual, no activation) ----
    cudaMemsetAsync(p_lmax, 0xFF, 8 * sizeof(float));
    gemm_fused_kernel<<<ggrid, 128>>>(f_h2, W2, f_feat, HD, al2, ar2);
    agg_kernel<<<NN, 128>>>(f_h2, f_h1, 1, 0);

    // ---- readout + classifier ----
    readout_kernel<<<NN / 8, 256>>>(f_h1, gid);
    classifier_kernel<<<1, GGR * CC>>>(Wc, bc, out);
}

// round 3
// speedup vs baseline: 1.4640x; 1.0577x over previous
#include <cuda_runtime.h>
#include <cuda_bf16.h>

#define NN 40000
#define EE 400000
#define GGR 64
#define IN_DIM 128
#define DD 64
#define HH 4
#define CC 10
#define HD 256   // H*D

// ---------------- static device scratch ----------------
__device__ float g_feat[NN * HD];
__device__ float g_h1[NN * HD];
__device__ float g_h2[NN * HD];
__device__ float g_el[NN * HH];
__device__ float g_er[NN * HH];
__device__ float g_lmax[8];        // [0..3]=el max per head, [4..7]=er max per head
__device__ float g_w[EE * HH];     // per-edge unnormalized softmax weight (CSR order)
__device__ int   g_counts[NN];
__device__ int   g_rowptr[NN + 1];
__device__ int   g_cursor[NN];
__device__ int   g_esrc[EE];       // src node per CSR slot (dst-grouped)
__device__ int   g_edst[EE];       // dst node per CSR slot
__device__ float g_hg[GGR * DD];
__device__ float g_cnt[GGR];

__device__ __forceinline__ void atomicMaxFloat(float* addr, float value) {
    if (value >= 0.f)
        atomicMax((int*)addr, __float_as_int(value));
    else
        atomicMin((unsigned int*)addr, __float_as_uint(value));
}

// ---------------- CSR build ----------------
__global__ void hist_kernel(const int* __restrict__ dst) {
    int t = blockIdx.x * blockDim.x + threadIdx.x;
    if (t < EE) atomicAdd(&g_counts[dst[t]], 1);
}

__global__ void scan_kernel() {
    __shared__ int sh[1024];
    const int PER = 40;  // 1024*40 >= NN
    int t = threadIdx.x;
    int base = t * PER;
    int s = 0;
    for (int k = 0; k < PER; k++) {
        int idx = base + k;
        if (idx < NN) s += g_counts[idx];
    }
    sh[t] = s;
    __syncthreads();
    for (int off = 1; off < 1024; off <<= 1) {
        int v = (t >= off) ? sh[t - off] : 0;
        __syncthreads();
        sh[t] += v;
        __syncthreads();
    }
    int run = (t > 0) ? sh[t - 1] : 0;
    if (t == 0) g_rowptr[0] = 0;
    for (int k = 0; k < PER; k++) {
        int idx = base + k;
        if (idx < NN) {
            run += g_counts[idx];
            g_rowptr[idx + 1] = run;
        }
    }
}

__global__ void scatter_kernel(const int* __restrict__ dst, const int* __restrict__ src) {
    int t = blockIdx.x * blockDim.x + threadIdx.x;
    if (t < EE) {
        int d = dst[t];
        int pos = g_rowptr[d] + atomicAdd(&g_cursor[d], 1);
        g_esrc[pos] = src[t];
        g_edst[pos] = d;
    }
}

// ---------------- GEMM + fused el/er epilogue (double-buffered) ----------------
// C[M,256] = A[M,K]*B[K,256]; tile 64x64, BK=16, 128 threads, 8x4 microtile.
__global__ void gemm_fused_kernel(const float* __restrict__ A, const float* __restrict__ B,
                                  float* __restrict__ C, int K,
                                  const float* __restrict__ al, const float* __restrict__ arv) {
    __shared__ float As[2][16][68];
    __shared__ float Bs[2][16][68];
    __shared__ float redl[16], redr[16];
    const int bm = blockIdx.y * 64;
    const int h  = blockIdx.x;
    const int bn = h * 64;
    const int tid = threadIdx.x;
    const int tx = tid & 15;
    const int ty = tid >> 4;
    const int a_row = tid >> 2;   // 0..31 (+u*32)
    const int a_c   = tid & 3;
    const int b_row = tid >> 3;   // 0..15
    const int b_c   = tid & 7;

    float acc[8][4] = {};
    float4 a_reg[2], b_reg[2];

    // prologue: load tile 0
#pragma unroll
    for (int u = 0; u < 2; u++)
        a_reg[u] = *(const float4*)&A[(size_t)(bm + a_row + u * 32) * K + a_c * 4];
#pragma unroll
    for (int u = 0; u < 2; u++)
        b_reg[u] = *(const float4*)&B[(size_t)b_row * HD + bn + (b_c + u * 8) * 4];

    int nk = K / 16;
    for (int kt = 0; kt < nk; kt++) {
        int buf = kt & 1;
#pragma unroll
        for (int u = 0; u < 2; u++) {
            int row = a_row + u * 32;
            As[buf][a_c * 4 + 0][row] = a_reg[u].x;
            As[buf][a_c * 4 + 1][row] = a_reg[u].y;
            As[buf][a_c * 4 + 2][row] = a_reg[u].z;
            As[buf][a_c * 4 + 3][row] = a_reg[u].w;
            *(float4*)&Bs[buf][b_row][(b_c + u * 8) * 4] = b_reg[u];
        }
        __syncthreads();
        if (kt + 1 < nk) {
            int k0 = (kt + 1) * 16;
#pragma unroll
            for (int u = 0; u < 2; u++)
                a_reg[u] = *(const float4*)&A[(size_t)(bm + a_row + u * 32) * K + k0 + a_c * 4];
#pragma unroll
            for (int u = 0; u < 2; u++)
                b_reg[u] = *(const float4*)&B[(size_t)(k0 + b_row) * HD + bn + (b_c + u * 8) * 4];
        }
#pragma unroll
        for (int k = 0; k < 16; k++) {
            float4 av0 = *(const float4*)&As[buf][k][ty * 8];
            float4 av1 = *(const float4*)&As[buf][k][ty * 8 + 4];
            float4 bv  = *(const float4*)&Bs[buf][k][tx * 4];
            float am[8] = {av0.x, av0.y, av0.z, av0.w, av1.x, av1.y, av1.z, av1.w};
            float bb[4] = {bv.x, bv.y, bv.z, bv.w};
#pragma unroll
            for (int i = 0; i < 8; i++)
#pragma unroll
                for (int j = 0; j < 4; j++)
                    acc[i][j] = fmaf(am[i], bb[j], acc[i][j]);
        }
        __syncthreads();
    }

#pragma unroll
    for (int i = 0; i < 8; i++) {
        float4 r = make_float4(acc[i][0], acc[i][1], acc[i][2], acc[i][3]);
        *(float4*)&C[(size_t)(bm + ty * 8 + i) * HD + bn + tx * 4] = r;
    }

    // fused el/er epilogue
    float4 alv = *(const float4*)&al[h * DD + tx * 4];
    float4 arw = *(const float4*)&arv[h * DD + tx * 4];
    float pls[8], prs[8];
#pragma unroll
    for (int i = 0; i < 8; i++) {
        float pl = acc[i][0] * alv.x + acc[i][1] * alv.y + acc[i][2] * alv.z + acc[i][3] * alv.w;
        float pr = acc[i][0] * arw.x + acc[i][1] * arw.y + acc[i][2] * arw.z + acc[i][3] * arw.w;
#pragma unroll
        for (int off = 8; off; off >>= 1) {
            pl += __shfl_xor_sync(0xffffffffu, pl, off);
            pr += __shfl_xor_sync(0xffffffffu, pr, off);
        }
        pls[i] = pl;
        prs[i] = pr;
    }
    if (tx == 0) {
        float mxl = -1e30f, mxr = -1e30f;
#pragma unroll
        for (int i = 0; i < 8; i++) {
            int n = bm + ty * 8 + i;
            g_el[n * HH + h] = pls[i];
            g_er[n * HH + h] = prs[i];
            mxl = fmaxf(mxl, pls[i]);
            mxr = fmaxf(mxr, prs[i]);
        }
        redl[ty] = mxl;
        redr[ty] = mxr;
    }
    __syncthreads();
    if (tid == 0) {
        float ml = -1e30f, mr = -1e30f;
#pragma unroll
        for (int i = 0; i < 16; i++) {
            ml = fmaxf(ml, redl[i]);
            mr = fmaxf(mr, redr[i]);
        }
        atomicMaxFloat(&g_lmax[h], ml);
        atomicMaxFloat(&g_lmax[4 + h], mr);
    }
}

// ---------------- per-edge softmax weights (all 4 heads at once) ----------------
__global__ void wcalc_kernel() {
    int p = blockIdx.x * blockDim.x + threadIdx.x;
    if (p >= EE) return;
    int s = g_esrc[p], d = g_edst[p];
    float4 el = *(const float4*)&g_el[s * HH];
    float4 er = *(const float4*)&g_er[d * HH];
    float4 w;
    float M0 = fmaxf(g_lmax[0] + g_lmax[4], 0.f);
    float M1 = fmaxf(g_lmax[1] + g_lmax[5], 0.f);
    float M2 = fmaxf(g_lmax[2] + g_lmax[6], 0.f);
    float M3 = fmaxf(g_lmax[3] + g_lmax[7], 0.f);
    float e0 = el.x + er.x, e1 = el.y + er.y, e2 = el.z + er.z, e3 = el.w + er.w;
    e0 = e0 > 0.f ? e0 : 0.2f * e0;
    e1 = e1 > 0.f ? e1 : 0.2f * e1;
    e2 = e2 > 0.f ? e2 : 0.2f * e2;
    e3 = e3 > 0.f ? e3 : 0.2f * e3;
    w.x = __expf(e0 - M0);
    w.y = __expf(e1 - M1);
    w.z = __expf(e2 - M2);
    w.w = __expf(e3 - M3);
    *(float4*)&g_w[p * HH] = w;
}

// ---------------- aggregation: shuffle-broadcast gather, high MLP ----------------
// one block per node, 4 warps = 4 heads
__global__ void agg_kernel(const float* __restrict__ hin, float* __restrict__ hout,
                           int residual, int activate) {
    int n = blockIdx.x;
    int h = threadIdx.x >> 5;
    int lane = threadIdx.x & 31;
    int s0 = g_rowptr[n], s1 = g_rowptr[n + 1];

    float a0 = 0.f, a1 = 0.f, sw = 0.f;
    for (int base = s0; base < s1; base += 32) {
        int cnt = min(32, s1 - base);
        int sidx = 0;
        float w = 0.f;
        if (lane < cnt) {
            sidx = g_esrc[base + lane];
            w = g_w[(base + lane) * HH + h];
        }
        sw += w;
#pragma unroll 4
        for (int j = 0; j < cnt; j++) {
            int sj = __shfl_sync(0xffffffffu, sidx, j);
            float wj = __shfl_sync(0xffffffffu, w, j);
            const float* f = &g_feat[(size_t)sj * HD + h * DD];
            a0 = fmaf(wj, f[lane], a0);
            a1 = fmaf(wj, f[lane + 32], a1);
        }
    }
#pragma unroll
    for (int off = 16; off; off >>= 1)
        sw += __shfl_xor_sync(0xffffffffu, sw, off);

    float inv = 1.f / fmaxf(sw, 1e-9f);
    float o0 = a0 * inv, o1 = a1 * inv;
    size_t outb = (size_t)n * HD + h * DD;
    if (residual) {
        o0 += hin[outb + lane];
        o1 += hin[outb + lane + 32];
    }
    if (activate) {
        o0 = o0 > 0.f ? o0 : (__expf(o0) - 1.f);
        o1 = o1 > 0.f ? o1 : (__expf(o1) - 1.f);
    }
    hout[outb + lane] = o0;
    hout[outb + lane + 32] = o1;
}

// ---------------- readout: run-accumulate over sorted graph_id ----------------
__global__ void readout_kernel(const float* __restrict__ hfin, const int* __restrict__ gid) {
    // block 256 = 8 warps; each warp handles 8 consecutive nodes
    int warp = threadIdx.x >> 5;
    int lane = threadIdx.x & 31;
    int base_n = (blockIdx.x * 8 + warp) * 8;
    if (base_n >= NN) return;
    float acc0 = 0.f, acc1 = 0.f;
    int cur = gid[base_n];
    int cnt = 0;
#pragma unroll
    for (int k = 0; k < 8; k++) {
        int n = base_n + k;
        if (n >= NN) break;
        int g = gid[n];
        if (g != cur) {
            atomicAdd(&g_hg[cur * DD + lane], acc0);
            atomicAdd(&g_hg[cur * DD + lane + 32], acc1);
            if (lane == 0) atomicAdd(&g_cnt[cur], (float)cnt);
            cur = g; acc0 = acc1 = 0.f; cnt = 0;
        }
        const float* f = &hfin[(size_t)n * HD];
        acc0 += 0.25f * (f[lane] + f[DD + lane] + f[2 * DD + lane] + f[3 * DD + lane]);
        acc1 += 0.25f * (f[lane + 32] + f[DD + lane + 32] + f[2 * DD + lane + 32] + f[3 * DD + lane + 32]);
        cnt++;
    }
    atomicAdd(&g_hg[cur * DD + lane], acc0);
    atomicAdd(&g_hg[cur * DD + lane + 32], acc1);
    if (lane == 0) atomicAdd(&g_cnt[cur], (float)cnt);
}

__global__ void classifier_kernel(const float* __restrict__ Wc, const float* __restrict__ bc,
                                  float* __restrict__ out) {
    int t = threadIdx.x;
    if (t >= GGR * CC) return;
    int g = t / CC, c = t % CC;
    float s = 0.f;
#pragma unroll
    for (int d = 0; d < DD; d++) s += g_hg[g * DD + d] * Wc[d * CC + c];
    out[t] = s / fmaxf(g_cnt[g], 1.0f) + bc[c];
}

// ---------------- host ----------------
extern "C" void kernel_launch(void* const* d_in, const int* in_sizes, int n_in,
                              void* d_out, int out_size) {
    const float* x   = (const float*)d_in[0];
    const int*   src = (const int*)d_in[1];
    const int*   dst = (const int*)d_in[2];
    const int*   gid = (const int*)d_in[3];
    const float* W0  = (const float*)d_in[4];
    const float* al0 = (const float*)d_in[5];
    const float* ar0 = (const float*)d_in[6];
    const float* W1  = (const float*)d_in[7];
    const float* al1 = (const float*)d_in[8];
    const float* ar1 = (const float*)d_in[9];
    const float* W2  = (const float*)d_in[10];
    const float* al2 = (const float*)d_in[11];
    const float* ar2 = (const float*)d_in[12];
    const float* Wc  = (const float*)d_in[13];
    const float* bc  = (const float*)d_in[14];
    float* out = (float*)d_out;

    void *p_counts, *p_cursor, *p_hg, *p_cnt, *p_feat, *p_h1, *p_h2, *p_lmax;
    cudaGetSymbolAddress(&p_counts, g_counts);
    cudaGetSymbolAddress(&p_cursor, g_cursor);
    cudaGetSymbolAddress(&p_hg, g_hg);
    cudaGetSymbolAddress(&p_cnt, g_cnt);
    cudaGetSymbolAddress(&p_feat, g_feat);
    cudaGetSymbolAddress(&p_h1, g_h1);
    cudaGetSymbolAddress(&p_h2, g_h2);
    cudaGetSymbolAddress(&p_lmax, g_lmax);
    float* f_feat = (float*)p_feat;
    float* f_h1 = (float*)p_h1;
    float* f_h2 = (float*)p_h2;

    // CSR build (once; same graph for all 3 layers)
    cudaMemsetAsync(p_counts, 0, NN * sizeof(int));
    cudaMemsetAsync(p_cursor, 0, NN * sizeof(int));
    cudaMemsetAsync(p_hg, 0, GGR * DD * sizeof(float));
    cudaMemsetAsync(p_cnt, 0, GGR * sizeof(float));
    hist_kernel<<<(EE + 255) / 256, 256>>>(dst);
    scan_kernel<<<1, 1024>>>();
    scatter_kernel<<<(EE + 255) / 256, 256>>>(dst, src);

    dim3 ggrid(HH, NN / 64);

    // ---- layer 0 ----
    cudaMemsetAsync(p_lmax, 0xFF, 8 * sizeof(float));
    gemm_fused_kernel<<<ggrid, 128>>>(x, W0, f_feat, IN_DIM, al0, ar0);
    wcalc_kernel<<<(EE + 255) / 256, 256>>>();
    agg_kernel<<<NN, 128>>>(nullptr, f_h1, 0, 1);

    // ---- layer 1 (residual) ----
    cudaMemsetAsync(p_lmax, 0xFF, 8 * sizeof(float));
    gemm_fused_kernel<<<ggrid, 128>>>(f_h1, W1, f_feat, HD, al1, ar1);
    wcalc_kernel<<<(EE + 255) / 256, 256>>>();
    agg_kernel<<<NN, 128>>>(f_h1, f_h2, 1, 1);

    // ---- layer 2 (residual, no activation) ----
    cudaMemsetAsync(p_lmax, 0xFF, 8 * sizeof(float));
    gemm_fused_kernel<<<ggrid, 128>>>(f_h2, W2, f_feat, HD, al2, ar2);
    wcalc_kernel<<<(EE + 255) / 256, 256>>>();
    agg_kernel<<<NN, 128>>>(f_h2, f_h1, 1, 0);

    // ---- readout + classifier ----
    readout_kernel<<<(NN + 63) / 64, 256>>>(f_h1, gid);
    classifier_kernel<<<1, GGR * CC>>>(Wc, bc, out);
}

// round 5
// speedup vs baseline: 1.9212x; 1.3122x over previous
#include <cuda_runtime.h>
#include <cuda_bf16.h>
#include <cstdint>

#define NN 40000
#define EE 400000
#define GGR 64
#define IN_DIM 128
#define DD 64
#define HH 4
#define CC 10
#define HD 256      // H*D
#define MTILES 313  // ceil(40000/128)
#define MPAD (MTILES * 128)

// ---------------- static device scratch ----------------
__device__ float g_feat[NN * HD];
__device__ float g_h1[NN * HD];
__device__ float g_h2[NN * HD];
__device__ float g_el[NN * HH];
__device__ float g_er[NN * HH];
__device__ float g_lmax[8];
__device__ float g_w[HH * EE];          // head-major per-edge weights
__device__ int   g_counts[NN];
__device__ int   g_rowptr[NN + 1];
__device__ int   g_cursor[NN];
__device__ int   g_esrc[EE];
__device__ int   g_edst[EE];
__device__ float g_hg[GGR * DD];
__device__ float g_cnt[GGR];
// fragment-packed bf16 operands (hi/lo split), mma.sync m16n8k16 layout
__device__ __nv_bfloat16 g_Ahi[MPAD * HD];
__device__ __nv_bfloat16 g_Alo[MPAD * HD];
__device__ __nv_bfloat16 g_Bhi[HH * DD * HD];
__device__ __nv_bfloat16 g_Blo[HH * DD * HD];

__device__ __forceinline__ void atomicMaxFloat(float* addr, float value) {
    if (value >= 0.f)
        atomicMax((int*)addr, __float_as_int(value));
    else
        atomicMin((unsigned int*)addr, __float_as_uint(value));
}

__device__ __forceinline__ uint32_t pack_bf2(__nv_bfloat16 lo, __nv_bfloat16 hi) {
    return (uint32_t)__bfloat16_as_ushort(lo) | ((uint32_t)__bfloat16_as_ushort(hi) << 16);
}

// index (in bf16 elements) of A element (m, k) inside the fragment-packed array, K = row width
__device__ __forceinline__ size_t a_frag_idx(int m, int k, int K) {
    int mt = m >> 4, rr = m & 15;
    int kt = k >> 4, cin = k & 15;
    int g = rr & 7;
    int r = (rr >> 3) | ((cin >> 3) << 1);
    int lane = g * 4 + ((cin & 6) >> 1);
    int tile = mt * (K >> 4) + kt;
    return ((size_t)(tile * 32 + lane) * 4 + r) * 2 + (cin & 1);
}

__device__ __forceinline__ void mma_bf16(float* c, const uint32_t* a, const uint32_t* b) {
    asm volatile(
        "mma.sync.aligned.m16n8k16.row.col.f32.bf16.bf16.f32 "
        "{%0,%1,%2,%3}, {%4,%5,%6,%7}, {%8,%9}, {%0,%1,%2,%3};"
        : "+f"(c[0]), "+f"(c[1]), "+f"(c[2]), "+f"(c[3])
        : "r"(a[0]), "r"(a[1]), "r"(a[2]), "r"(a[3]), "r"(b[0]), "r"(b[1]));
}

// ---------------- CSR build ----------------
__global__ void hist_kernel(const int* __restrict__ dst) {
    int t = blockIdx.x * blockDim.x + threadIdx.x;
    if (t < EE) atomicAdd(&g_counts[dst[t]], 1);
}

__global__ void scan_kernel() {
    __shared__ int sh[1024];
    const int PER = 40;
    int t = threadIdx.x;
    int base = t * PER;
    int s = 0;
    for (int k = 0; k < PER; k++) {
        int idx = base + k;
        if (idx < NN) s += g_counts[idx];
    }
    sh[t] = s;
    __syncthreads();
    for (int off = 1; off < 1024; off <<= 1) {
        int v = (t >= off) ? sh[t - off] : 0;
        __syncthreads();
        sh[t] += v;
        __syncthreads();
    }
    int run = (t > 0) ? sh[t - 1] : 0;
    if (t == 0) g_rowptr[0] = 0;
    for (int k = 0; k < PER; k++) {
        int idx = base + k;
        if (idx < NN) {
            run += g_counts[idx];
            g_rowptr[idx + 1] = run;
        }
    }
}

__global__ void scatter_kernel(const int* __restrict__ dst, const int* __restrict__ src) {
    int t = blockIdx.x * blockDim.x + threadIdx.x;
    if (t < EE) {
        int d = dst[t];
        int pos = g_rowptr[d] + atomicAdd(&g_cursor[d], 1);
        g_esrc[pos] = src[t];
        g_edst[pos] = d;
    }
}

// ---------------- prep: x -> A fragments (K=128, rows padded with zeros) ----------------
__global__ void prep_x_kernel(const float* __restrict__ x) {
    const int KT = IN_DIM / 16;
    int idx = blockIdx.x * blockDim.x + threadIdx.x;
    int total = (MPAD / 16) * KT * 32;
    if (idx >= total) return;
    int lane = idx & 31;
    int tile = idx >> 5;
    int kt = tile % KT, mt = tile / KT;
    int g = lane >> 2, t2 = (lane & 3) * 2;
    uint32_t hi[4], lo[4];
#pragma unroll
    for (int r = 0; r < 4; r++) {
        int m = mt * 16 + g + ((r & 1) << 3);
        int k = kt * 16 + t2 + ((r >> 1) << 3);
        float v0 = (m < NN) ? x[(size_t)m * IN_DIM + k] : 0.f;
        float v1 = (m < NN) ? x[(size_t)m * IN_DIM + k + 1] : 0.f;
        __nv_bfloat16 h0 = __float2bfloat16(v0);
        __nv_bfloat16 h1 = __float2bfloat16(v1);
        __nv_bfloat16 l0 = __float2bfloat16(v0 - __bfloat162float(h0));
        __nv_bfloat16 l1 = __float2bfloat16(v1 - __bfloat162float(h1));
        hi[r] = pack_bf2(h0, h1);
        lo[r] = pack_bf2(l0, l1);
    }
    ((uint4*)g_Ahi)[tile * 32 + lane] = *(uint4*)hi;
    ((uint4*)g_Alo)[tile * 32 + lane] = *(uint4*)lo;
}

// ---------------- prep: W[K,256] -> B fragments per head ----------------
__global__ void prep_w_kernel(const float* __restrict__ W, int K) {
    int KT = K / 16;
    int idx = blockIdx.x * blockDim.x + threadIdx.x;
    int total = HH * KT * 8 * 32;
    if (idx >= total) return;
    int lane = idx & 31;
    int tile = idx >> 5;          // tile = (h*KT + kt)*8 + nt
    int nt = tile & 7;
    int hk = tile >> 3;
    int kt = hk % KT, h = hk / KT;
    int g = lane >> 2, t2 = (lane & 3) * 2;
    uint32_t hi[2], lo[2];
#pragma unroll
    for (int r = 0; r < 2; r++) {
        int k = kt * 16 + t2 + r * 8;
        int n = h * DD + nt * 8 + g;
        float v0 = W[(size_t)k * HD + n];
        float v1 = W[(size_t)(k + 1) * HD + n];
        __nv_bfloat16 h0 = __float2bfloat16(v0);
        __nv_bfloat16 h1 = __float2bfloat16(v1);
        __nv_bfloat16 l0 = __float2bfloat16(v0 - __bfloat162float(h0));
        __nv_bfloat16 l1 = __float2bfloat16(v1 - __bfloat162float(h1));
        hi[r] = pack_bf2(h0, h1);
        lo[r] = pack_bf2(l0, l1);
    }
    ((uint2*)g_Bhi)[tile * 32 + lane] = *(uint2*)hi;
    ((uint2*)g_Blo)[tile * 32 + lane] = *(uint2*)lo;
}

// ---------------- HMMA GEMM + fused el/er epilogue ----------------
// grid (HH, MTILES), 256 threads = 8 warps; warp w computes m-atom (by*8+w): 16 rows x 64 cols.
template <int K>
__global__ void __launch_bounds__(256, 2)
hmma_gemm_kernel(const float* __restrict__ al, const float* __restrict__ arv) {
    const int KT = K / 16;
    __shared__ float al_s[64], ar_s[64];
    int tid = threadIdx.x, w = tid >> 5, lane = tid & 31;
    int h = blockIdx.x;
    int mt = blockIdx.y * 8 + w;
    if (tid < 64) al_s[tid] = al[h * DD + tid];
    else if (tid < 128) ar_s[tid - 64] = arv[h * DD + tid - 64];
    __syncthreads();

    const uint4* Ah4 = (const uint4*)g_Ahi;
    const uint4* Al4 = (const uint4*)g_Alo;
    const uint2* Bh2 = (const uint2*)g_Bhi;
    const uint2* Bl2 = (const uint2*)g_Blo;

    float acc[8][4] = {};
#pragma unroll 2
    for (int kt = 0; kt < KT; kt++) {
        uint4 a_h = Ah4[(mt * KT + kt) * 32 + lane];
        uint4 a_l = Al4[(mt * KT + kt) * 32 + lane];
        uint2 b_h[8], b_l[8];
        int tb = ((h * KT + kt) * 8) * 32 + lane;
#pragma unroll
        for (int nt = 0; nt < 8; nt++) {
            b_h[nt] = Bh2[tb + nt * 32];
            b_l[nt] = Bl2[tb + nt * 32];
        }
#pragma unroll
        for (int nt = 0; nt < 8; nt++) {
            mma_bf16(acc[nt], (const uint32_t*)&a_h, (const uint32_t*)&b_h[nt]);
            mma_bf16(acc[nt], (const uint32_t*)&a_h, (const uint32_t*)&b_l[nt]);
            mma_bf16(acc[nt], (const uint32_t*)&a_l, (const uint32_t*)&b_h[nt]);
        }
    }

    // epilogue: write feat + fused el/er
    int g = lane >> 2, t2 = (lane & 3) * 2;
    int row0 = mt * 16 + g, row1 = row0 + 8;
    float el0 = 0.f, el1 = 0.f, er0 = 0.f, er1 = 0.f;
#pragma unroll
    for (int nt = 0; nt < 8; nt++) {
        int cb = nt * 8 + t2;
        float a0 = al_s[cb], a1 = al_s[cb + 1];
        float r0 = ar_s[cb], r1 = ar_s[cb + 1];
        el0 += acc[nt][0] * a0 + acc[nt][1] * a1;
        er0 += acc[nt][0] * r0 + acc[nt][1] * r1;
        el1 += acc[nt][2] * a0 + acc[nt][3] * a1;
        er1 += acc[nt][2] * r0 + acc[nt][3] * r1;
        if (row0 < NN)
            *(float2*)&g_feat[(size_t)row0 * HD + h * DD + cb] = make_float2(acc[nt][0], acc[nt][1]);
        if (row1 < NN)
            *(float2*)&g_feat[(size_t)row1 * HD + h * DD + cb] = make_float2(acc[nt][2], acc[nt][3]);
    }
#pragma unroll
    for (int off = 1; off <= 2; off <<= 1) {
        el0 += __shfl_xor_sync(0xffffffffu, el0, off);
        el1 += __shfl_xor_sync(0xffffffffu, el1, off);
        er0 += __shfl_xor_sync(0xffffffffu, er0, off);
        er1 += __shfl_xor_sync(0xffffffffu, er1, off);
    }
    if ((lane & 3) == 0) {
        if (row0 < NN) { g_el[row0 * HH + h] = el0; g_er[row0 * HH + h] = er0; }
        if (row1 < NN) { g_el[row1 * HH + h] = el1; g_er[row1 * HH + h] = er1; }
    }
    float ml = fmaxf(row0 < NN ? el0 : -1e30f, row1 < NN ? el1 : -1e30f);
    float mr = fmaxf(row0 < NN ? er0 : -1e30f, row1 < NN ? er1 : -1e30f);
#pragma unroll
    for (int off = 16; off; off >>= 1) {
        ml = fmaxf(ml, __shfl_xor_sync(0xffffffffu, ml, off));
        mr = fmaxf(mr, __shfl_xor_sync(0xffffffffu, mr, off));
    }
    if (lane == 0) {
        atomicMaxFloat(&g_lmax[h], ml);
        atomicMaxFloat(&g_lmax[4 + h], mr);
    }
}

// ---------------- per-edge softmax weights (head-major output) ----------------
__global__ void wcalc_kernel() {
    int p = blockIdx.x * blockDim.x + threadIdx.x;
    if (p >= EE) return;
    int s = g_esrc[p], d = g_edst[p];
    float4 el = *(const float4*)&g_el[s * HH];
    float4 er = *(const float4*)&g_er[d * HH];
    float M0 = fmaxf(g_lmax[0] + g_lmax[4], 0.f);
    float M1 = fmaxf(g_lmax[1] + g_lmax[5], 0.f);
    float M2 = fmaxf(g_lmax[2] + g_lmax[6], 0.f);
    float M3 = fmaxf(g_lmax[3] + g_lmax[7], 0.f);
    float e0 = el.x + er.x, e1 = el.y + er.y, e2 = el.z + er.z, e3 = el.w + er.w;
    e0 = e0 > 0.f ? e0 : 0.2f * e0;
    e1 = e1 > 0.f ? e1 : 0.2f * e1;
    e2 = e2 > 0.f ? e2 : 0.2f * e2;
    e3 = e3 > 0.f ? e3 : 0.2f * e3;
    g_w[0 * EE + p] = __expf(e0 - M0);
    g_w[1 * EE + p] = __expf(e1 - M1);
    g_w[2 * EE + p] = __expf(e2 - M2);
    g_w[3 * EE + p] = __expf(e3 - M3);
}

// ---------------- aggregation + fused next-layer fragment emit ----------------
__global__ void agg_kernel(const float* __restrict__ hin, float* __restrict__ hout,
                           int residual, int activate, int write_bf16) {
    int n = blockIdx.x;
    int h = threadIdx.x >> 5;
    int lane = threadIdx.x & 31;

    float o0 = 0.f, o1 = 0.f;
    if (n < NN) {
        int s0 = g_rowptr[n], s1 = g_rowptr[n + 1];
        float a0 = 0.f, a1 = 0.f, sw = 0.f;
        for (int base = s0; base < s1; base += 32) {
            int cnt = min(32, s1 - base);
            int sidx = 0;
            float w = 0.f;
            if (lane < cnt) {
                sidx = g_esrc[base + lane];
                w = g_w[h * EE + base + lane];
            }
            sw += w;
#pragma unroll 4
            for (int j = 0; j < cnt; j++) {
                int sj = __shfl_sync(0xffffffffu, sidx, j);
                float wj = __shfl_sync(0xffffffffu, w, j);
                const float* f = &g_feat[(size_t)sj * HD + h * DD];
                a0 = fmaf(wj, f[lane], a0);
                a1 = fmaf(wj, f[lane + 32], a1);
            }
        }
#pragma unroll
        for (int off = 16; off; off >>= 1)
            sw += __shfl_xor_sync(0xffffffffu, sw, off);
        float inv = 1.f / fmaxf(sw, 1e-9f);
        o0 = a0 * inv;
        o1 = a1 * inv;
        size_t outb = (size_t)n * HD + h * DD;
        if (residual) {
            o0 += hin[outb + lane];
            o1 += hin[outb + lane + 32];
        }
        if (activate) {
            o0 = o0 > 0.f ? o0 : (__expf(o0) - 1.f);
            o1 = o1 > 0.f ? o1 : (__expf(o1) - 1.f);
        }
        hout[outb + lane] = o0;
        hout[outb + lane + 32] = o1;
    }
    if (write_bf16) {
        size_t i0 = a_frag_idx(n, h * DD + lane, HD);
        size_t i1 = a_frag_idx(n, h * DD + lane + 32, HD);
        __nv_bfloat16 h0 = __float2bfloat16(o0);
        __nv_bfloat16 l0 = __float2bfloat16(o0 - __bfloat162float(h0));
        __nv_bfloat16 h1 = __float2bfloat16(o1);
        __nv_bfloat16 l1 = __float2bfloat16(o1 - __bfloat162float(h1));
        g_Ahi[i0] = h0; g_Alo[i0] = l0;
        g_Ahi[i1] = h1; g_Alo[i1] = l1;
    }
}

// ---------------- readout + classifier ----------------
__global__ void readout_kernel(const float* __restrict__ hfin, const int* __restrict__ gid) {
    int warp = threadIdx.x >> 5;
    int lane = threadIdx.x & 31;
    int base_n = (blockIdx.x * 8 + warp) * 8;
    if (base_n >= NN) return;
    float acc0 = 0.f, acc1 = 0.f;
    int cur = gid[base_n];
    int cnt = 0;
#pragma unroll
    for (int k = 0; k < 8; k++) {
        int n = base_n + k;
        if (n >= NN) break;
        int g = gid[n];
        if (g != cur) {
            atomicAdd(&g_hg[cur * DD + lane], acc0);
            atomicAdd(&g_hg[cur * DD + lane + 32], acc1);
            if (lane == 0) atomicAdd(&g_cnt[cur], (float)cnt);
            cur = g; acc0 = acc1 = 0.f; cnt = 0;
        }
        const float* f = &hfin[(size_t)n * HD];
        acc0 += 0.25f * (f[lane] + f[DD + lane] + f[2 * DD + lane] + f[3 * DD + lane]);
        acc1 += 0.25f * (f[lane + 32] + f[DD + lane + 32] + f[2 * DD + lane + 32] + f[3 * DD + lane + 32]);
        cnt++;
    }
    atomicAdd(&g_hg[cur * DD + lane], acc0);
    atomicAdd(&g_hg[cur * DD + lane + 32], acc1);
    if (lane == 0) atomicAdd(&g_cnt[cur], (float)cnt);
}

__global__ void classifier_kernel(const float* __restrict__ Wc, const float* __restrict__ bc,
                                  float* __restrict__ out) {
    int t = threadIdx.x;
    if (t >= GGR * CC) return;
    int g = t / CC, c = t % CC;
    float s = 0.f;
#pragma unroll
    for (int d = 0; d < DD; d++) s += g_hg[g * DD + d] * Wc[d * CC + c];
    out[t] = s / fmaxf(g_cnt[g], 1.0f) + bc[c];
}

// ---------------- host ----------------
extern "C" void kernel_launch(void* const* d_in, const int* in_sizes, int n_in,
                              void* d_out, int out_size) {
    const float* x   = (const float*)d_in[0];
    const int*   src = (const int*)d_in[1];
    const int*   dst = (const int*)d_in[2];
    const int*   gid = (const int*)d_in[3];
    const float* W0  = (const float*)d_in[4];
    const float* al0 = (const float*)d_in[5];
    const float* ar0 = (const float*)d_in[6];
    const float* W1  = (const float*)d_in[7];
    const float* al1 = (const float*)d_in[8];
    const float* ar1 = (const float*)d_in[9];
    const float* W2  = (const float*)d_in[10];
    const float* al2 = (const float*)d_in[11];
    const float* ar2 = (const float*)d_in[12];
    const float* Wc  = (const float*)d_in[13];
    const float* bc  = (const float*)d_in[14];
    float* out = (float*)d_out;

    void *p_counts, *p_cursor, *p_hg, *p_cnt, *p_h1, *p_h2, *p_lmax;
    cudaGetSymbolAddress(&p_counts, g_counts);
    cudaGetSymbolAddress(&p_cursor, g_cursor);
    cudaGetSymbolAddress(&p_hg, g_hg);
    cudaGetSymbolAddress(&p_cnt, g_cnt);
    cudaGetSymbolAddress(&p_h1, g_h1);
    cudaGetSymbolAddress(&p_h2, g_h2);
    cudaGetSymbolAddress(&p_lmax, g_lmax);
    float* f_h1 = (float*)p_h1;
    float* f_h2 = (float*)p_h2;

    // CSR build
    cudaMemsetAsync(p_counts, 0, NN * sizeof(int));
    cudaMemsetAsync(p_cursor, 0, NN * sizeof(int));
    cudaMemsetAsync(p_hg, 0, GGR * DD * sizeof(float));
    cudaMemsetAsync(p_cnt, 0, GGR * sizeof(float));
    hist_kernel<<<(EE + 255) / 256, 256>>>(dst);
    scan_kernel<<<1, 1024>>>();
    scatter_kernel<<<(EE + 255) / 256, 256>>>(dst, src);

    dim3 mgrid(HH, MTILES);

    // ---- layer 0 (K=128) ----
    cudaMemsetAsync(p_lmax, 0xFF, 8 * sizeof(float));
    prep_x_kernel<<<((MPAD / 16) * (IN_DIM / 16) * 32 + 255) / 256, 256>>>(x);
    prep_w_kernel<<<(HH * (IN_DIM / 16) * 8 * 32 + 255) / 256, 256>>>(W0, IN_DIM);
    hmma_gemm_kernel<IN_DIM><<<mgrid, 256>>>(al0, ar0);
    wcalc_kernel<<<(EE + 255) / 256, 256>>>();
    agg_kernel<<<MPAD, 128>>>(nullptr, f_h1, 0, 1, 1);

    // ---- layer 1 (K=256, residual) ----
    cudaMemsetAsync(p_lmax, 0xFF, 8 * sizeof(float));
    prep_w_kernel<<<(HH * (HD / 16) * 8 * 32 + 255) / 256, 256>>>(W1, HD);
    hmma_gemm_kernel<HD><<<mgrid, 256>>>(al1, ar1);
    wcalc_kernel<<<(EE + 255) / 256, 256>>>();
    agg_kernel<<<MPAD, 128>>>(f_h1, f_h2, 1, 1, 1);

    // ---- layer 2 (K=256, residual, no activation) ----
    cudaMemsetAsync(p_lmax, 0xFF, 8 * sizeof(float));
    prep_w_kernel<<<(HH * (HD / 16) * 8 * 32 + 255) / 256, 256>>>(W2, HD);
    hmma_gemm_kernel<HD><<<mgrid, 256>>>(al2, ar2);
    wcalc_kernel<<<(EE + 255) / 256, 256>>>();
    agg_kernel<<<NN, 128>>>(f_h2, f_h1, 1, 0, 0);

    // ---- readout + classifier ----
    readout_kernel<<<(NN + 63) / 64, 256>>>(f_h1, gid);
    classifier_kernel<<<1, GGR * CC>>>(Wc, bc, out);
}

// round 6
// speedup vs baseline: 2.0348x; 1.0591x over previous
#include <cuda_runtime.h>
#include <cuda_bf16.h>
#include <cuda_fp16.h>
#include <cstdint>

#define NN 40000
#define EE 400000
#define GGR 64
#define IN_DIM 128
#define DD 64
#define HH 4
#define CC 10
#define HD 256      // H*D
#define MTILES 313  // ceil(40000/128)
#define MPAD (MTILES * 128)

// ---------------- static device scratch ----------------
__device__ __half g_feat16[NN * HD];    // fp16 mirror of projected features (gather source)
__device__ float g_h1[NN * HD];
__device__ float g_h2[NN * HD];
__device__ float g_el[NN * HH];
__device__ float g_er[NN * HH];
__device__ float g_lmax[8];
__device__ float g_w[HH * EE];          // head-major per-edge weights
__device__ int   g_counts[NN];
__device__ int   g_rowptr[NN + 1];
__device__ int   g_cursor[NN];
__device__ int   g_esrc[EE];
__device__ int   g_edst[EE];
__device__ float g_hg[GGR * DD];
__device__ float g_cnt[GGR];
// fragment-packed bf16 operands (hi/lo split), mma.sync m16n8k16 layout
__device__ __nv_bfloat16 g_Ahi[MPAD * HD];
__device__ __nv_bfloat16 g_Alo[MPAD * HD];
__device__ __nv_bfloat16 g_Bhi[HH * DD * HD];
__device__ __nv_bfloat16 g_Blo[HH * DD * HD];

__device__ __forceinline__ void atomicMaxFloat(float* addr, float value) {
    if (value >= 0.f)
        atomicMax((int*)addr, __float_as_int(value));
    else
        atomicMin((unsigned int*)addr, __float_as_uint(value));
}

__device__ __forceinline__ uint32_t pack_bf2(__nv_bfloat16 lo, __nv_bfloat16 hi) {
    return (uint32_t)__bfloat16_as_ushort(lo) | ((uint32_t)__bfloat16_as_ushort(hi) << 16);
}

// index (bf16 elements) of A element (m, k) inside fragment-packed array; K = row width
__device__ __forceinline__ size_t a_frag_idx(int m, int k, int K) {
    int mt = m >> 4, rr = m & 15;
    int kt = k >> 4, cin = k & 15;
    int g = rr & 7;
    int r = (rr >> 3) | ((cin >> 3) << 1);
    int lane = g * 4 + ((cin & 6) >> 1);
    int tile = mt * (K >> 4) + kt;
    return ((size_t)(tile * 32 + lane) * 4 + r) * 2 + (cin & 1);
}

__device__ __forceinline__ void mma_bf16(float* c, const uint32_t* a, const uint32_t* b) {
    asm volatile(
        "mma.sync.aligned.m16n8k16.row.col.f32.bf16.bf16.f32 "
        "{%0,%1,%2,%3}, {%4,%5,%6,%7}, {%8,%9}, {%0,%1,%2,%3};"
        : "+f"(c[0]), "+f"(c[1]), "+f"(c[2]), "+f"(c[3])
        : "r"(a[0]), "r"(a[1]), "r"(a[2]), "r"(a[3]), "r"(b[0]), "r"(b[1]));
}

// ---------------- CSR build ----------------
__global__ void hist_kernel(const int* __restrict__ dst) {
    int t = blockIdx.x * blockDim.x + threadIdx.x;
    if (t < EE) atomicAdd(&g_counts[dst[t]], 1);
}

__global__ void scan_kernel() {
    __shared__ int sh[1024];
    const int PER = 40;
    int t = threadIdx.x;
    int base = t * PER;
    int s = 0;
    for (int k = 0; k < PER; k++) {
        int idx = base + k;
        if (idx < NN) s += g_counts[idx];
    }
    sh[t] = s;
    __syncthreads();
    for (int off = 1; off < 1024; off <<= 1) {
        int v = (t >= off) ? sh[t - off] : 0;
        __syncthreads();
        sh[t] += v;
        __syncthreads();
    }
    int run = (t > 0) ? sh[t - 1] : 0;
    if (t == 0) g_rowptr[0] = 0;
    for (int k = 0; k < PER; k++) {
        int idx = base + k;
        if (idx < NN) {
            run += g_counts[idx];
            g_rowptr[idx + 1] = run;
        }
    }
}

__global__ void scatter_kernel(const int* __restrict__ dst, const int* __restrict__ src) {
    int t = blockIdx.x * blockDim.x + threadIdx.x;
    if (t < EE) {
        int d = dst[t];
        int pos = g_rowptr[d] + atomicAdd(&g_cursor[d], 1);
        g_esrc[pos] = src[t];
        g_edst[pos] = d;
    }
}

// ---------------- prep: x -> A fragments (K=128, rows padded with zeros) ----------------
__global__ void prep_x_kernel(const float* __restrict__ x) {
    const int KT = IN_DIM / 16;
    int idx = blockIdx.x * blockDim.x + threadIdx.x;
    int total = (MPAD / 16) * KT * 32;
    if (idx >= total) return;
    int lane = idx & 31;
    int tile = idx >> 5;
    int kt = tile % KT, mt = tile / KT;
    int g = lane >> 2, t2 = (lane & 3) * 2;
    uint32_t hi[4], lo[4];
#pragma unroll
    for (int r = 0; r < 4; r++) {
        int m = mt * 16 + g + ((r & 1) << 3);
        int k = kt * 16 + t2 + ((r >> 1) << 3);
        float v0 = (m < NN) ? x[(size_t)m * IN_DIM + k] : 0.f;
        float v1 = (m < NN) ? x[(size_t)m * IN_DIM + k + 1] : 0.f;
        __nv_bfloat16 h0 = __float2bfloat16(v0);
        __nv_bfloat16 h1 = __float2bfloat16(v1);
        __nv_bfloat16 l0 = __float2bfloat16(v0 - __bfloat162float(h0));
        __nv_bfloat16 l1 = __float2bfloat16(v1 - __bfloat162float(h1));
        hi[r] = pack_bf2(h0, h1);
        lo[r] = pack_bf2(l0, l1);
    }
    ((uint4*)g_Ahi)[tile * 32 + lane] = *(uint4*)hi;
    ((uint4*)g_Alo)[tile * 32 + lane] = *(uint4*)lo;
}

// ---------------- prep: W[K,256] -> B fragments per head ----------------
__global__ void prep_w_kernel(const float* __restrict__ W, int K) {
    int KT = K / 16;
    int idx = blockIdx.x * blockDim.x + threadIdx.x;
    int total = HH * KT * 8 * 32;
    if (idx >= total) return;
    int lane = idx & 31;
    int tile = idx >> 5;          // tile = (h*KT + kt)*8 + nt
    int nt = tile & 7;
    int hk = tile >> 3;
    int kt = hk % KT, h = hk / KT;
    int g = lane >> 2, t2 = (lane & 3) * 2;
    uint32_t hi[2], lo[2];
#pragma unroll
    for (int r = 0; r < 2; r++) {
        int k = kt * 16 + t2 + r * 8;
        int n = h * DD + nt * 8 + g;
        float v0 = W[(size_t)k * HD + n];
        float v1 = W[(size_t)(k + 1) * HD + n];
        __nv_bfloat16 h0 = __float2bfloat16(v0);
        __nv_bfloat16 h1 = __float2bfloat16(v1);
        __nv_bfloat16 l0 = __float2bfloat16(v0 - __bfloat162float(h0));
        __nv_bfloat16 l1 = __float2bfloat16(v1 - __bfloat162float(h1));
        hi[r] = pack_bf2(h0, h1);
        lo[r] = pack_bf2(l0, l1);
    }
    ((uint2*)g_Bhi)[tile * 32 + lane] = *(uint2*)hi;
    ((uint2*)g_Blo)[tile * 32 + lane] = *(uint2*)lo;
}

// ---------------- HMMA GEMM + fused el/er + fp16 feature emit ----------------
// grid (HH, MTILES), 256 threads = 8 warps; warp w: 16 rows x 64 cols.
template <int K>
__global__ void __launch_bounds__(256, 2)
hmma_gemm_kernel(const float* __restrict__ al, const float* __restrict__ arv) {
    const int KT = K / 16;
    __shared__ float al_s[64], ar_s[64];
    int tid = threadIdx.x, w = tid >> 5, lane = tid & 31;
    int h = blockIdx.x;
    int mt = blockIdx.y * 8 + w;
    if (tid < 64) al_s[tid] = al[h * DD + tid];
    else if (tid < 128) ar_s[tid - 64] = arv[h * DD + tid - 64];
    __syncthreads();

    const uint4* Ah4 = (const uint4*)g_Ahi;
    const uint4* Al4 = (const uint4*)g_Alo;
    const uint2* Bh2 = (const uint2*)g_Bhi;
    const uint2* Bl2 = (const uint2*)g_Blo;

    float acc[8][4] = {};
#pragma unroll 2
    for (int kt = 0; kt < KT; kt++) {
        uint4 a_h = Ah4[(mt * KT + kt) * 32 + lane];
        uint4 a_l = Al4[(mt * KT + kt) * 32 + lane];
        uint2 b_h[8], b_l[8];
        int tb = ((h * KT + kt) * 8) * 32 + lane;
#pragma unroll
        for (int nt = 0; nt < 8; nt++) {
            b_h[nt] = Bh2[tb + nt * 32];
            b_l[nt] = Bl2[tb + nt * 32];
        }
#pragma unroll
        for (int nt = 0; nt < 8; nt++) {
            mma_bf16(acc[nt], (const uint32_t*)&a_h, (const uint32_t*)&b_h[nt]);
            mma_bf16(acc[nt], (const uint32_t*)&a_h, (const uint32_t*)&b_l[nt]);
            mma_bf16(acc[nt], (const uint32_t*)&a_l, (const uint32_t*)&b_h[nt]);
        }
    }

    // epilogue: fp16 feature emit + fused el/er
    int g = lane >> 2, t2 = (lane & 3) * 2;
    int row0 = mt * 16 + g, row1 = row0 + 8;
    half2* F = (half2*)g_feat16;
    float el0 = 0.f, el1 = 0.f, er0 = 0.f, er1 = 0.f;
#pragma unroll
    for (int nt = 0; nt < 8; nt++) {
        int cb = nt * 8 + t2;
        float a0 = al_s[cb], a1 = al_s[cb + 1];
        float r0 = ar_s[cb], r1 = ar_s[cb + 1];
        el0 += acc[nt][0] * a0 + acc[nt][1] * a1;
        er0 += acc[nt][0] * r0 + acc[nt][1] * r1;
        el1 += acc[nt][2] * a0 + acc[nt][3] * a1;
        er1 += acc[nt][2] * r0 + acc[nt][3] * r1;
        int cidx = (h * DD + cb) >> 1;
        if (row0 < NN) F[row0 * (HD / 2) + cidx] = __floats2half2_rn(acc[nt][0], acc[nt][1]);
        if (row1 < NN) F[row1 * (HD / 2) + cidx] = __floats2half2_rn(acc[nt][2], acc[nt][3]);
    }
#pragma unroll
    for (int off = 1; off <= 2; off <<= 1) {
        el0 += __shfl_xor_sync(0xffffffffu, el0, off);
        el1 += __shfl_xor_sync(0xffffffffu, el1, off);
        er0 += __shfl_xor_sync(0xffffffffu, er0, off);
        er1 += __shfl_xor_sync(0xffffffffu, er1, off);
    }
    if ((lane & 3) == 0) {
        if (row0 < NN) { g_el[row0 * HH + h] = el0; g_er[row0 * HH + h] = er0; }
        if (row1 < NN) { g_el[row1 * HH + h] = el1; g_er[row1 * HH + h] = er1; }
    }
    float ml = fmaxf(row0 < NN ? el0 : -1e30f, row1 < NN ? el1 : -1e30f);
    float mr = fmaxf(row0 < NN ? er0 : -1e30f, row1 < NN ? er1 : -1e30f);
#pragma unroll
    for (int off = 16; off; off >>= 1) {
        ml = fmaxf(ml, __shfl_xor_sync(0xffffffffu, ml, off));
        mr = fmaxf(mr, __shfl_xor_sync(0xffffffffu, mr, off));
    }
    if (lane == 0) {
        atomicMaxFloat(&g_lmax[h], ml);
        atomicMaxFloat(&g_lmax[4 + h], mr);
    }
}

// ---------------- per-edge softmax weights (head-major output) ----------------
__global__ void wcalc_kernel() {
    int p = blockIdx.x * blockDim.x + threadIdx.x;
    if (p >= EE) return;
    int s = g_esrc[p], d = g_edst[p];
    float4 el = *(const float4*)&g_el[s * HH];
    float4 er = *(const float4*)&g_er[d * HH];
    float M0 = fmaxf(g_lmax[0] + g_lmax[4], 0.f);
    float M1 = fmaxf(g_lmax[1] + g_lmax[5], 0.f);
    float M2 = fmaxf(g_lmax[2] + g_lmax[6], 0.f);
    float M3 = fmaxf(g_lmax[3] + g_lmax[7], 0.f);
    float e0 = el.x + er.x, e1 = el.y + er.y, e2 = el.z + er.z, e3 = el.w + er.w;
    e0 = e0 > 0.f ? e0 : 0.2f * e0;
    e1 = e1 > 0.f ? e1 : 0.2f * e1;
    e2 = e2 > 0.f ? e2 : 0.2f * e2;
    e3 = e3 > 0.f ? e3 : 0.2f * e3;
    g_w[0 * EE + p] = __expf(e0 - M0);
    g_w[1 * EE + p] = __expf(e1 - M1);
    g_w[2 * EE + p] = __expf(e2 - M2);
    g_w[3 * EE + p] = __expf(e3 - M3);
}

// ---------------- aggregation (fp16 gather) + fused next-layer fragment emit ----------------
// one block per node, 4 warps = 4 heads; lane owns column pair (2*lane, 2*lane+1)
__global__ void agg_kernel(const float* __restrict__ hin, float* __restrict__ hout,
                           int residual, int activate, int write_bf16) {
    int n = blockIdx.x;
    int h = threadIdx.x >> 5;
    int lane = threadIdx.x & 31;
    const half2* F = (const half2*)g_feat16;

    float o0 = 0.f, o1 = 0.f;
    if (n < NN) {
        int s0 = g_rowptr[n], s1 = g_rowptr[n + 1];
        float a0 = 0.f, a1 = 0.f, sw = 0.f;
        for (int base = s0; base < s1; base += 32) {
            int cnt = min(32, s1 - base);
            int sidx = 0;
            float w = 0.f;
            if (lane < cnt) {
                sidx = g_esrc[base + lane];
                w = g_w[h * EE + base + lane];
            }
            sw += w;
#pragma unroll 8
            for (int j = 0; j < cnt; j++) {
                int sj = __shfl_sync(0xffffffffu, sidx, j);
                float wj = __shfl_sync(0xffffffffu, w, j);
                float2 vf = __half22float2(F[sj * (HD / 2) + h * 32 + lane]);
                a0 = fmaf(wj, vf.x, a0);
                a1 = fmaf(wj, vf.y, a1);
            }
        }
#pragma unroll
        for (int off = 16; off; off >>= 1)
            sw += __shfl_xor_sync(0xffffffffu, sw, off);
        float inv = 1.f / fmaxf(sw, 1e-9f);
        o0 = a0 * inv;
        o1 = a1 * inv;
        size_t outb = (size_t)n * HD + h * DD + 2 * lane;
        if (residual) {
            float2 r = *(const float2*)&hin[outb];
            o0 += r.x;
            o1 += r.y;
        }
        if (activate) {
            o0 = o0 > 0.f ? o0 : (__expf(o0) - 1.f);
            o1 = o1 > 0.f ? o1 : (__expf(o1) - 1.f);
        }
        *(float2*)&hout[outb] = make_float2(o0, o1);
    }
    if (write_bf16) {
        int k0 = h * DD + 2 * lane;
        size_t i0 = a_frag_idx(n, k0, HD);  // even; covers k0 (lo) and k0+1 (hi)
        __nv_bfloat16 h0 = __float2bfloat16(o0);
        __nv_bfloat16 l0 = __float2bfloat16(o0 - __bfloat162float(h0));
        __nv_bfloat16 h1 = __float2bfloat16(o1);
        __nv_bfloat16 l1 = __float2bfloat16(o1 - __bfloat162float(h1));
        ((uint32_t*)g_Ahi)[i0 >> 1] = pack_bf2(h0, h1);
        ((uint32_t*)g_Alo)[i0 >> 1] = pack_bf2(l0, l1);
    }
}

// ---------------- readout + classifier ----------------
__global__ void readout_kernel(const float* __restrict__ hfin, const int* __restrict__ gid) {
    int warp = threadIdx.x >> 5;
    int lane = threadIdx.x & 31;
    int base_n = (blockIdx.x * 8 + warp) * 8;
    if (base_n >= NN) return;
    float acc0 = 0.f, acc1 = 0.f;
    int cur = gid[base_n];
    int cnt = 0;
#pragma unroll
    for (int k = 0; k < 8; k++) {
        int n = base_n + k;
        if (n >= NN) break;
        int g = gid[n];
        if (g != cur) {
            atomicAdd(&g_hg[cur * DD + lane], acc0);
            atomicAdd(&g_hg[cur * DD + lane + 32], acc1);
            if (lane == 0) atomicAdd(&g_cnt[cur], (float)cnt);
            cur = g; acc0 = acc1 = 0.f; cnt = 0;
        }
        const float* f = &hfin[(size_t)n * HD];
        acc0 += 0.25f * (f[lane] + f[DD + lane] + f[2 * DD + lane] + f[3 * DD + lane]);
        acc1 += 0.25f * (f[lane + 32] + f[DD + lane + 32] + f[2 * DD + lane + 32] + f[3 * DD + lane + 32]);
        cnt++;
    }
    atomicAdd(&g_hg[cur * DD + lane], acc0);
    atomicAdd(&g_hg[cur * DD + lane + 32], acc1);
    if (lane == 0) atomicAdd(&g_cnt[cur], (float)cnt);
}

__global__ void classifier_kernel(const float* __restrict__ Wc, const float* __restrict__ bc,
                                  float* __restrict__ out) {
    int t = threadIdx.x;
    if (t >= GGR * CC) return;
    int g = t / CC, c = t % CC;
    float s = 0.f;
#pragma unroll
    for (int d = 0; d < DD; d++) s += g_hg[g * DD + d] * Wc[d * CC + c];
    out[t] = s / fmaxf(g_cnt[g], 1.0f) + bc[c];
}

// ---------------- host ----------------
extern "C" void kernel_launch(void* const* d_in, const int* in_sizes, int n_in,
                              void* d_out, int out_size) {
    const float* x   = (const float*)d_in[0];
    const int*   src = (const int*)d_in[1];
    const int*   dst = (const int*)d_in[2];
    const int*   gid = (const int*)d_in[3];
    const float* W0  = (const float*)d_in[4];
    const float* al0 = (const float*)d_in[5];
    const float* ar0 = (const float*)d_in[6];
    const float* W1  = (const float*)d_in[7];
    const float* al1 = (const float*)d_in[8];
    const float* ar1 = (const float*)d_in[9];
    const float* W2  = (const float*)d_in[10];
    const float* al2 = (const float*)d_in[11];
    const float* ar2 = (const float*)d_in[12];
    const float* Wc  = (const float*)d_in[13];
    const float* bc  = (const float*)d_in[14];
    float* out = (float*)d_out;

    void *p_counts, *p_cursor, *p_hg, *p_cnt, *p_h1, *p_h2, *p_lmax;
    cudaGetSymbolAddress(&p_counts, g_counts);
    cudaGetSymbolAddress(&p_cursor, g_cursor);
    cudaGetSymbolAddress(&p_hg, g_hg);
    cudaGetSymbolAddress(&p_cnt, g_cnt);
    cudaGetSymbolAddress(&p_h1, g_h1);
    cudaGetSymbolAddress(&p_h2, g_h2);
    cudaGetSymbolAddress(&p_lmax, g_lmax);
    float* f_h1 = (float*)p_h1;
    float* f_h2 = (float*)p_h2;

    // CSR build
    cudaMemsetAsync(p_counts, 0, NN * sizeof(int));
    cudaMemsetAsync(p_cursor, 0, NN * sizeof(int));
    cudaMemsetAsync(p_hg, 0, GGR * DD * sizeof(float));
    cudaMemsetAsync(p_cnt, 0, GGR * sizeof(float));
    hist_kernel<<<(EE + 255) / 256, 256>>>(dst);
    scan_kernel<<<1, 1024>>>();
    scatter_kernel<<<(EE + 255) / 256, 256>>>(dst, src);

    dim3 mgrid(HH, MTILES);

    // ---- layer 0 (K=128) ----
    cudaMemsetAsync(p_lmax, 0xFF, 8 * sizeof(float));
    prep_x_kernel<<<((MPAD / 16) * (IN_DIM / 16) * 32 + 255) / 256, 256>>>(x);
    prep_w_kernel<<<(HH * (IN_DIM / 16) * 8 * 32 + 255) / 256, 256>>>(W0, IN_DIM);
    hmma_gemm_kernel<IN_DIM><<<mgrid, 256>>>(al0, ar0);
    wcalc_kernel<<<(EE + 255) / 256, 256>>>();
    agg_kernel<<<MPAD, 128>>>(nullptr, f_h1, 0, 1, 1);

    // ---- layer 1 (K=256, residual) ----
    cudaMemsetAsync(p_lmax, 0xFF, 8 * sizeof(float));
    prep_w_kernel<<<(HH * (HD / 16) * 8 * 32 + 255) / 256, 256>>>(W1, HD);
    hmma_gemm_kernel<HD><<<mgrid, 256>>>(al1, ar1);
    wcalc_kernel<<<(EE + 255) / 256, 256>>>();
    agg_kernel<<<MPAD, 128>>>(f_h1, f_h2, 1, 1, 1);

    // ---- layer 2 (K=256, residual, no activation) ----
    cudaMemsetAsync(p_lmax, 0xFF, 8 * sizeof(float));
    prep_w_kernel<<<(HH * (HD / 16) * 8 * 32 + 255) / 256, 256>>>(W2, HD);
    hmma_gemm_kernel<HD><<<mgrid, 256>>>(al2, ar2);
    wcalc_kernel<<<(EE + 255) / 256, 256>>>();
    agg_kernel<<<NN, 128>>>(f_h2, f_h1, 1, 0, 0);

    // ---- readout + classifier ----
    readout_kernel<<<(NN + 63) / 64, 256>>>(f_h1, gid);
    classifier_kernel<<<1, GGR * CC>>>(Wc, bc, out);
}

// round 7
// speedup vs baseline: 2.0657x; 1.0152x over previous
#include <cuda_runtime.h>
#include <cuda_bf16.h>
#include <cuda_fp16.h>
#include <cstdint>

#define NN 40000
#define EE 400000
#define GGR 64
#define IN_DIM 128
#define DD 64
#define HH 4
#define CC 10
#define HD 256      // H*D
#define MTILES 313  // ceil(40000/128)
#define MPAD (MTILES * 128)
#define SCAN_B 40   // scan blocks (40*1024 >= NN)

// ---------------- static device scratch ----------------
__device__ __half g_feat16[NN * HD];
__device__ float g_h1[NN * HD];
__device__ float g_h2[NN * HD];
__device__ float g_el[NN * HH];
__device__ float g_er[NN * HH];
__device__ float g_lmax[8];
__device__ float g_w[HH * EE];
__device__ int   g_counts[NN];
__device__ int   g_rowptr[NN + 1];
__device__ int   g_cursor[NN];
__device__ int   g_bsum[SCAN_B];
__device__ int   g_esrc[EE];
__device__ int   g_edst[EE];
__device__ float g_hg[GGR * DD];
__device__ float g_cnt[GGR];
__device__ __nv_bfloat16 g_Ahi[MPAD * HD];
__device__ __nv_bfloat16 g_Alo[MPAD * HD];
__device__ __nv_bfloat16 g_Bhi[HH * DD * HD];
__device__ __nv_bfloat16 g_Blo[HH * DD * HD];

__device__ __forceinline__ void atomicMaxFloat(float* addr, float value) {
    if (value >= 0.f)
        atomicMax((int*)addr, __float_as_int(value));
    else
        atomicMin((unsigned int*)addr, __float_as_uint(value));
}

__device__ __forceinline__ uint32_t pack_bf2(__nv_bfloat16 lo, __nv_bfloat16 hi) {
    return (uint32_t)__bfloat16_as_ushort(lo) | ((uint32_t)__bfloat16_as_ushort(hi) << 16);
}

__device__ __forceinline__ size_t a_frag_idx(int m, int k, int K) {
    int mt = m >> 4, rr = m & 15;
    int kt = k >> 4, cin = k & 15;
    int g = rr & 7;
    int r = (rr >> 3) | ((cin >> 3) << 1);
    int lane = g * 4 + ((cin & 6) >> 1);
    int tile = mt * (K >> 4) + kt;
    return ((size_t)(tile * 32 + lane) * 4 + r) * 2 + (cin & 1);
}

__device__ __forceinline__ void mma_bf16(float* c, const uint32_t* a, const uint32_t* b) {
    asm volatile(
        "mma.sync.aligned.m16n8k16.row.col.f32.bf16.bf16.f32 "
        "{%0,%1,%2,%3}, {%4,%5,%6,%7}, {%8,%9}, {%0,%1,%2,%3};"
        : "+f"(c[0]), "+f"(c[1]), "+f"(c[2]), "+f"(c[3])
        : "r"(a[0]), "r"(a[1]), "r"(a[2]), "r"(a[3]), "r"(b[0]), "r"(b[1]));
}

// ---------------- init + CSR build ----------------
__global__ void zero_kernel() {
    int t = blockIdx.x * blockDim.x + threadIdx.x;
    if (t < NN) { g_counts[t] = 0; g_cursor[t] = 0; }
    if (t < GGR * DD) g_hg[t] = 0.f;
    if (t < GGR) g_cnt[t] = 0.f;
}

__global__ void hist_kernel(const int* __restrict__ dst) {
    int t = blockIdx.x * blockDim.x + threadIdx.x;
    if (t < EE) atomicAdd(&g_counts[dst[t]], 1);
}

// phase 1: per-block sums (coalesced)
__global__ void scan1_kernel() {
    __shared__ int sh[1024];
    int t = threadIdx.x;
    int idx = blockIdx.x * 1024 + t;
    int v = (idx < NN) ? g_counts[idx] : 0;
    sh[t] = v;
    __syncthreads();
    for (int off = 512; off; off >>= 1) {
        if (t < off) sh[t] += sh[t + off];
        __syncthreads();
    }
    if (t == 0) g_bsum[blockIdx.x] = sh[0];
}

// phase 2: exclusive scan of block sums (1 warp)
__global__ void scan2_kernel() {
    int t = threadIdx.x;
    int v = (t < SCAN_B) ? g_bsum[t] : 0;
    int s = v;
#pragma unroll
    for (int off = 1; off < 64; off <<= 1) {
        int u = __shfl_up_sync(0xffffffffffffffffull & 0xffffffffu, s, off);
        if ((t & 63) >= off) s += u;
    }
    // blockDim = 64: do shared-based scan instead (warp-size safety)
    __shared__ int sh[64];
    sh[t] = v;
    __syncthreads();
    for (int off = 1; off < 64; off <<= 1) {
        int add = (t >= off) ? sh[t - off] : 0;
        __syncthreads();
        sh[t] += add;
        __syncthreads();
    }
    if (t < SCAN_B) g_bsum[t] = sh[t] - v;  // exclusive
}

// phase 3: intra-block scan + offset -> rowptr
__global__ void scan3_kernel() {
    __shared__ int sh[1024];
    int t = threadIdx.x;
    int idx = blockIdx.x * 1024 + t;
    int v = (idx < NN) ? g_counts[idx] : 0;
    sh[t] = v;
    __syncthreads();
    for (int off = 1; off < 1024; off <<= 1) {
        int add = (t >= off) ? sh[t - off] : 0;
        __syncthreads();
        sh[t] += add;
        __syncthreads();
    }
    int off = g_bsum[blockIdx.x];
    if (idx < NN) g_rowptr[idx + 1] = off + sh[t];
    if (idx == 0) g_rowptr[0] = 0;
}

__global__ void scatter_kernel(const int* __restrict__ dst, const int* __restrict__ src) {
    int t = blockIdx.x * blockDim.x + threadIdx.x;
    if (t < EE) {
        int d = dst[t];
        int pos = g_rowptr[d] + atomicAdd(&g_cursor[d], 1);
        g_esrc[pos] = src[t];
        g_edst[pos] = d;
    }
}

// ---------------- prep kernels ----------------
__global__ void prep_x_kernel(const float* __restrict__ x) {
    const int KT = IN_DIM / 16;
    int idx = blockIdx.x * blockDim.x + threadIdx.x;
    int total = (MPAD / 16) * KT * 32;
    if (idx >= total) return;
    int lane = idx & 31;
    int tile = idx >> 5;
    int kt = tile % KT, mt = tile / KT;
    int g = lane >> 2, t2 = (lane & 3) * 2;
    uint32_t hi[4], lo[4];
#pragma unroll
    for (int r = 0; r < 4; r++) {
        int m = mt * 16 + g + ((r & 1) << 3);
        int k = kt * 16 + t2 + ((r >> 1) << 3);
        float v0 = (m < NN) ? x[(size_t)m * IN_DIM + k] : 0.f;
        float v1 = (m < NN) ? x[(size_t)m * IN_DIM + k + 1] : 0.f;
        __nv_bfloat16 h0 = __float2bfloat16(v0);
        __nv_bfloat16 h1 = __float2bfloat16(v1);
        __nv_bfloat16 l0 = __float2bfloat16(v0 - __bfloat162float(h0));
        __nv_bfloat16 l1 = __float2bfloat16(v1 - __bfloat162float(h1));
        hi[r] = pack_bf2(h0, h1);
        lo[r] = pack_bf2(l0, l1);
    }
    ((uint4*)g_Ahi)[tile * 32 + lane] = *(uint4*)hi;
    ((uint4*)g_Alo)[tile * 32 + lane] = *(uint4*)lo;
}

__global__ void prep_w_kernel(const float* __restrict__ W, int K) {
    int KT = K / 16;
    int idx = blockIdx.x * blockDim.x + threadIdx.x;
    if (idx < 8) g_lmax[idx] = -1e30f;   // fused lmax reset
    int total = HH * KT * 8 * 32;
    if (idx >= total) return;
    int lane = idx & 31;
    int tile = idx >> 5;
    int nt = tile & 7;
    int hk = tile >> 3;
    int kt = hk % KT, h = hk / KT;
    int g = lane >> 2, t2 = (lane & 3) * 2;
    uint32_t hi[2], lo[2];
#pragma unroll
    for (int r = 0; r < 2; r++) {
        int k = kt * 16 + t2 + r * 8;
        int n = h * DD + nt * 8 + g;
        float v0 = W[(size_t)k * HD + n];
        float v1 = W[(size_t)(k + 1) * HD + n];
        __nv_bfloat16 h0 = __float2bfloat16(v0);
        __nv_bfloat16 h1 = __float2bfloat16(v1);
        __nv_bfloat16 l0 = __float2bfloat16(v0 - __bfloat162float(h0));
        __nv_bfloat16 l1 = __float2bfloat16(v1 - __bfloat162float(h1));
        hi[r] = pack_bf2(h0, h1);
        lo[r] = pack_bf2(l0, l1);
    }
    ((uint2*)g_Bhi)[tile * 32 + lane] = *(uint2*)hi;
    ((uint2*)g_Blo)[tile * 32 + lane] = *(uint2*)lo;
}

// ---------------- HMMA GEMM + fused el/er + fp16 feature emit ----------------
template <int K>
__global__ void __launch_bounds__(256, 2)
hmma_gemm_kernel(const float* __restrict__ al, const float* __restrict__ arv) {
    const int KT = K / 16;
    __shared__ float al_s[64], ar_s[64];
    int tid = threadIdx.x, w = tid >> 5, lane = tid & 31;
    int h = blockIdx.x;
    int mt = blockIdx.y * 8 + w;
    if (tid < 64) al_s[tid] = al[h * DD + tid];
    else if (tid < 128) ar_s[tid - 64] = arv[h * DD + tid - 64];
    __syncthreads();

    const uint4* Ah4 = (const uint4*)g_Ahi;
    const uint4* Al4 = (const uint4*)g_Alo;
    const uint2* Bh2 = (const uint2*)g_Bhi;
    const uint2* Bl2 = (const uint2*)g_Blo;

    float acc[8][4] = {};
#pragma unroll 2
    for (int kt = 0; kt < KT; kt++) {
        uint4 a_h = Ah4[(mt * KT + kt) * 32 + lane];
        uint4 a_l = Al4[(mt * KT + kt) * 32 + lane];
        uint2 b_h[8], b_l[8];
        int tb = ((h * KT + kt) * 8) * 32 + lane;
#pragma unroll
        for (int nt = 0; nt < 8; nt++) {
            b_h[nt] = Bh2[tb + nt * 32];
            b_l[nt] = Bl2[tb + nt * 32];
        }
#pragma unroll
        for (int nt = 0; nt < 8; nt++) {
            mma_bf16(acc[nt], (const uint32_t*)&a_h, (const uint32_t*)&b_h[nt]);
            mma_bf16(acc[nt], (const uint32_t*)&a_h, (const uint32_t*)&b_l[nt]);
            mma_bf16(acc[nt], (const uint32_t*)&a_l, (const uint32_t*)&b_h[nt]);
        }
    }

    int g = lane >> 2, t2 = (lane & 3) * 2;
    int row0 = mt * 16 + g, row1 = row0 + 8;
    half2* F = (half2*)g_feat16;
    float el0 = 0.f, el1 = 0.f, er0 = 0.f, er1 = 0.f;
#pragma unroll
    for (int nt = 0; nt < 8; nt++) {
        int cb = nt * 8 + t2;
        float a0 = al_s[cb], a1 = al_s[cb + 1];
        float r0 = ar_s[cb], r1 = ar_s[cb + 1];
        el0 += acc[nt][0] * a0 + acc[nt][1] * a1;
        er0 += acc[nt][0] * r0 + acc[nt][1] * r1;
        el1 += acc[nt][2] * a0 + acc[nt][3] * a1;
        er1 += acc[nt][2] * r0 + acc[nt][3] * r1;
        int cidx = (h * DD + cb) >> 1;
        if (row0 < NN) F[row0 * (HD / 2) + cidx] = __floats2half2_rn(acc[nt][0], acc[nt][1]);
        if (row1 < NN) F[row1 * (HD / 2) + cidx] = __floats2half2_rn(acc[nt][2], acc[nt][3]);
    }
#pragma unroll
    for (int off = 1; off <= 2; off <<= 1) {
        el0 += __shfl_xor_sync(0xffffffffu, el0, off);
        el1 += __shfl_xor_sync(0xffffffffu, el1, off);
        er0 += __shfl_xor_sync(0xffffffffu, er0, off);
        er1 += __shfl_xor_sync(0xffffffffu, er1, off);
    }
    if ((lane & 3) == 0) {
        if (row0 < NN) { g_el[row0 * HH + h] = el0; g_er[row0 * HH + h] = er0; }
        if (row1 < NN) { g_el[row1 * HH + h] = el1; g_er[row1 * HH + h] = er1; }
    }
    float ml = fmaxf(row0 < NN ? el0 : -1e30f, row1 < NN ? el1 : -1e30f);
    float mr = fmaxf(row0 < NN ? er0 : -1e30f, row1 < NN ? er1 : -1e30f);
#pragma unroll
    for (int off = 16; off; off >>= 1) {
        ml = fmaxf(ml, __shfl_xor_sync(0xffffffffu, ml, off));
        mr = fmaxf(mr, __shfl_xor_sync(0xffffffffu, mr, off));
    }
    if (lane == 0) {
        atomicMaxFloat(&g_lmax[h], ml);
        atomicMaxFloat(&g_lmax[4 + h], mr);
    }
}

// ---------------- per-edge softmax weights ----------------
__global__ void wcalc_kernel() {
    int p = blockIdx.x * blockDim.x + threadIdx.x;
    if (p >= EE) return;
    int s = g_esrc[p], d = g_edst[p];
    float4 el = *(const float4*)&g_el[s * HH];
    float4 er = *(const float4*)&g_er[d * HH];
    float M0 = fmaxf(g_lmax[0] + g_lmax[4], 0.f);
    float M1 = fmaxf(g_lmax[1] + g_lmax[5], 0.f);
    float M2 = fmaxf(g_lmax[2] + g_lmax[6], 0.f);
    float M3 = fmaxf(g_lmax[3] + g_lmax[7], 0.f);
    float e0 = el.x + er.x, e1 = el.y + er.y, e2 = el.z + er.z, e3 = el.w + er.w;
    e0 = e0 > 0.f ? e0 : 0.2f * e0;
    e1 = e1 > 0.f ? e1 : 0.2f * e1;
    e2 = e2 > 0.f ? e2 : 0.2f * e2;
    e3 = e3 > 0.f ? e3 : 0.2f * e3;
    g_w[0 * EE + p] = __expf(e0 - M0);
    g_w[1 * EE + p] = __expf(e1 - M1);
    g_w[2 * EE + p] = __expf(e2 - M2);
    g_w[3 * EE + p] = __expf(e3 - M3);
}

// ---------------- aggregation (2 nodes / 256-thread block) ----------------
__global__ void __launch_bounds__(256, 6)
agg_kernel(const float* __restrict__ hin, float* __restrict__ hout,
           int residual, int activate, int write_bf16) {
    int n = blockIdx.x * 2 + (threadIdx.x >> 7);
    int h = (threadIdx.x >> 5) & 3;
    int lane = threadIdx.x & 31;
    const half2* F = (const half2*)g_feat16;

    float o0 = 0.f, o1 = 0.f;
    if (n < NN) {
        int s0 = __ldg(&g_rowptr[n]), s1 = __ldg(&g_rowptr[n + 1]);
        float a0 = 0.f, a1 = 0.f, sw = 0.f;
        for (int base = s0; base < s1; base += 32) {
            int cnt = min(32, s1 - base);
            int sidx = 0;
            float w = 0.f;
            if (lane < cnt) {
                sidx = __ldg(&g_esrc[base + lane]);
                w = __ldg(&g_w[h * EE + base + lane]);
            }
            sw += w;
#pragma unroll 8
            for (int j = 0; j < cnt; j++) {
                int sj = __shfl_sync(0xffffffffu, sidx, j);
                float wj = __shfl_sync(0xffffffffu, w, j);
                float2 vf = __half22float2(__ldg(&F[sj * (HD / 2) + h * 32 + lane]));
                a0 = fmaf(wj, vf.x, a0);
                a1 = fmaf(wj, vf.y, a1);
            }
        }
#pragma unroll
        for (int off = 16; off; off >>= 1)
            sw += __shfl_xor_sync(0xffffffffu, sw, off);
        float inv = 1.f / fmaxf(sw, 1e-9f);
        o0 = a0 * inv;
        o1 = a1 * inv;
        size_t outb = (size_t)n * HD + h * DD + 2 * lane;
        if (residual) {
            float2 r = *(const float2*)&hin[outb];
            o0 += r.x;
            o1 += r.y;
        }
        if (activate) {
            o0 = o0 > 0.f ? o0 : (__expf(o0) - 1.f);
            o1 = o1 > 0.f ? o1 : (__expf(o1) - 1.f);
        }
        *(float2*)&hout[outb] = make_float2(o0, o1);
    }
    if (write_bf16 && n < MPAD) {
        int k0 = h * DD + 2 * lane;
        size_t i0 = a_frag_idx(n, k0, HD);
        __nv_bfloat16 h0 = __float2bfloat16(o0);
        __nv_bfloat16 l0 = __float2bfloat16(o0 - __bfloat162float(h0));
        __nv_bfloat16 h1 = __float2bfloat16(o1);
        __nv_bfloat16 l1 = __float2bfloat16(o1 - __bfloat162float(h1));
        ((uint32_t*)g_Ahi)[i0 >> 1] = pack_bf2(h0, h1);
        ((uint32_t*)g_Alo)[i0 >> 1] = pack_bf2(l0, l1);
    }
}

// ---------------- readout + classifier ----------------
__global__ void readout_kernel(const float* __restrict__ hfin, const int* __restrict__ gid) {
    int warp = threadIdx.x >> 5;
    int lane = threadIdx.x & 31;
    int base_n = (blockIdx.x * 8 + warp) * 8;
    if (base_n >= NN) return;
    float acc0 = 0.f, acc1 = 0.f;
    int cur = gid[base_n];
    int cnt = 0;
#pragma unroll
    for (int k = 0; k < 8; k++) {
        int n = base_n + k;
        if (n >= NN) break;
        int g = gid[n];
        if (g != cur) {
            atomicAdd(&g_hg[cur * DD + lane], acc0);
            atomicAdd(&g_hg[cur * DD + lane + 32], acc1);
            if (lane == 0) atomicAdd(&g_cnt[cur], (float)cnt);
            cur = g; acc0 = acc1 = 0.f; cnt = 0;
        }
        const float* f = &hfin[(size_t)n * HD];
        acc0 += 0.25f * (f[lane] + f[DD + lane] + f[2 * DD + lane] + f[3 * DD + lane]);
        acc1 += 0.25f * (f[lane + 32] + f[DD + lane + 32] + f[2 * DD + lane + 32] + f[3 * DD + lane + 32]);
        cnt++;
    }
    atomicAdd(&g_hg[cur * DD + lane], acc0);
    atomicAdd(&g_hg[cur * DD + lane + 32], acc1);
    if (lane == 0) atomicAdd(&g_cnt[cur], (float)cnt);
}

__global__ void classifier_kernel(const float* __restrict__ Wc, const float* __restrict__ bc,
                                  float* __restrict__ out) {
    int t = threadIdx.x;
    if (t >= GGR * CC) return;
    int g = t / CC, c = t % CC;
    float s = 0.f;
#pragma unroll
    for (int d = 0; d < DD; d++) s += g_hg[g * DD + d] * Wc[d * CC + c];
    out[t] = s / fmaxf(g_cnt[g], 1.0f) + bc[c];
}

// ---------------- host ----------------
extern "C" void kernel_launch(void* const* d_in, const int* in_sizes, int n_in,
                              void* d_out, int out_size) {
    const float* x   = (const float*)d_in[0];
    const int*   src = (const int*)d_in[1];
    const int*   dst = (const int*)d_in[2];
    const int*   gid = (const int*)d_in[3];
    const float* W0  = (const float*)d_in[4];
    const float* al0 = (const float*)d_in[5];
    const float* ar0 = (const float*)d_in[6];
    const float* W1  = (const float*)d_in[7];
    const float* al1 = (const float*)d_in[8];
    const float* ar1 = (const float*)d_in[9];
    const float* W2  = (const float*)d_in[10];
    const float* al2 = (const float*)d_in[11];
    const float* ar2 = (const float*)d_in[12];
    const float* Wc  = (const float*)d_in[13];
    const float* bc  = (const float*)d_in[14];
    float* out = (float*)d_out;

    void *p_h1, *p_h2;
    cudaGetSymbolAddress(&p_h1, g_h1);
    cudaGetSymbolAddress(&p_h2, g_h2);
    float* f_h1 = (float*)p_h1;
    float* f_h2 = (float*)p_h2;

    // init + CSR build (no memsets; all fused into kernels)
    zero_kernel<<<(NN + 255) / 256, 256>>>();
    hist_kernel<<<(EE + 255) / 256, 256>>>(dst);
    scan1_kernel<<<SCAN_B, 1024>>>();
    scan2_kernel<<<1, 64>>>();
    scan3_kernel<<<SCAN_B, 1024>>>();
    scatter_kernel<<<(EE + 255) / 256, 256>>>(dst, src);

    dim3 mgrid(HH, MTILES);

    // ---- layer 0 (K=128) ----
    prep_x_kernel<<<((MPAD / 16) * (IN_DIM / 16) * 32 + 255) / 256, 256>>>(x);
    prep_w_kernel<<<(HH * (IN_DIM / 16) * 8 * 32 + 255) / 256, 256>>>(W0, IN_DIM);
    hmma_gemm_kernel<IN_DIM><<<mgrid, 256>>>(al0, ar0);
    wcalc_kernel<<<(EE + 255) / 256, 256>>>();
    agg_kernel<<<MPAD / 2, 256>>>(nullptr, f_h1, 0, 1, 1);

    // ---- layer 1 (K=256, residual) ----
    prep_w_kernel<<<(HH * (HD / 16) * 8 * 32 + 255) / 256, 256>>>(W1, HD);
    hmma_gemm_kernel<HD><<<mgrid, 256>>>(al1, ar1);
    wcalc_kernel<<<(EE + 255) / 256, 256>>>();
    agg_kernel<<<MPAD / 2, 256>>>(f_h1, f_h2, 1, 1, 1);

    // ---- layer 2 (K=256, residual, no activation) ----
    prep_w_kernel<<<(HH * (HD / 16) * 8 * 32 + 255) / 256, 256>>>(W2, HD);
    hmma_gemm_kernel<HD><<<mgrid, 256>>>(al2, ar2);
    wcalc_kernel<<<(EE + 255) / 256, 256>>>();
    agg_kernel<<<(NN + 1) / 2, 256>>>(f_h2, f_h1, 1, 0, 0);

    // ---- readout + classifier ----
    readout_kernel<<<(NN + 63) / 64, 256>>>(f_h1, gid);
    classifier_kernel<<<1, GGR * CC>>>(Wc, bc, out);
}